// round 11
// baseline (speedup 1.0000x reference)
#include <cuda_runtime.h>
#include <cuda_bf16.h>
#include <math.h>
#include <stdint.h>

// ---------------- problem constants ----------------
#define BATCH  2048
#define DDIM   32
#define HID    512
#define NSTEPS 16
#define NELEM  (BATCH * DDIM)

// ---------------- device scratch ----------------
__device__ __align__(16) __nv_bfloat16 g_h1_hi[BATCH * HID];
__device__ __align__(16) __nv_bfloat16 g_h1_lo[BATCH * HID];
__device__ __align__(16) float         g_theta2[2][NELEM];
__device__ __align__(16) float         g_ksum2 [2][NELEM];
__device__ __align__(16) float         g_kpart[8 * NELEM];
__device__ __align__(16) __nv_bfloat16 g_B1t_hi[1024 * 32];
__device__ __align__(16) __nv_bfloat16 g_B1t_lo[1024 * 32];
__device__ __align__(16) __nv_bfloat16 g_B1c_hi[1024 * 128];
__device__ __align__(16) __nv_bfloat16 g_B1c_lo[1024 * 128];
__device__ __align__(16) __nv_bfloat16 g_B2_hi[1024 * HID];
__device__ __align__(16) __nv_bfloat16 g_B2_lo[1024 * HID];
__device__ __align__(16) __nv_bfloat16 g_W3t_hi[DDIM * HID];
__device__ __align__(16) __nv_bfloat16 g_W3t_lo[DDIM * HID];
__device__ __align__(16) __nv_bfloat16 g_ctx_hi[BATCH * 128];
__device__ __align__(16) __nv_bfloat16 g_ctx_lo[BATCH * 128];
__device__ __align__(16) float         g_C0[BATCH * 1024];    // ctx@W1c + b1 (fp32)
__device__ int g_h1flag[16 * 8];                              // per (bm16, chunk)

// ---------------- PTX helpers (compute_100-safe) ----------------
__device__ __forceinline__ uint32_t smem_u32(const void* p) {
    uint32_t a;
    asm("{ .reg .u64 t; cvta.to.shared.u64 t, %1; cvt.u32.u64 %0, t; }"
        : "=r"(a) : "l"(p));
    return a;
}
__device__ __forceinline__ void cpasync16(uint32_t saddr, const void* g) {
    asm volatile("cp.async.cg.shared.global [%0], [%1], 16;"
                 :: "r"(saddr), "l"(g) : "memory");
}
#define CP_COMMIT() asm volatile("cp.async.commit_group;" ::: "memory")
#define CP_WAIT0()  asm volatile("cp.async.wait_group 0;" ::: "memory")
#define CP_WAIT1()  asm volatile("cp.async.wait_group 1;" ::: "memory")

__device__ __forceinline__ void ldsm4(uint32_t* r, uint32_t addr) {
    asm volatile("ldmatrix.sync.aligned.m8n8.x4.shared.b16 {%0,%1,%2,%3}, [%4];"
                 : "=r"(r[0]), "=r"(r[1]), "=r"(r[2]), "=r"(r[3]) : "r"(addr));
}
__device__ __forceinline__ void mma16816(float* c, const uint32_t* a, const uint32_t* b) {
    asm volatile("mma.sync.aligned.m16n8k16.row.col.f32.bf16.bf16.f32 "
                 "{%0,%1,%2,%3}, {%4,%5,%6,%7}, {%8,%9}, {%0,%1,%2,%3};"
                 : "+f"(c[0]), "+f"(c[1]), "+f"(c[2]), "+f"(c[3])
                 : "r"(a[0]), "r"(a[1]), "r"(a[2]), "r"(a[3]),
                   "r"(b[0]), "r"(b[1]));
}
__device__ __forceinline__ void bf16split(float v, __nv_bfloat16& h, __nv_bfloat16& l) {
    h = __float2bfloat16(v);
    l = __float2bfloat16(v - __bfloat162float(h));
}
__device__ __forceinline__ void flag_release(int* p, int v) {
    asm volatile("st.release.gpu.global.b32 [%0], %1;" :: "l"(p), "r"(v) : "memory");
}
__device__ __forceinline__ int flag_acquire(const int* p) {
    int v;
    asm volatile("ld.acquire.gpu.global.b32 %0, [%1];" : "=r"(v) : "l"(p) : "memory");
    return v;
}

// ---------------- init kernels ----------------
__global__ void init_b1t(const float* __restrict__ W1) {
    int idx = blockIdx.x * 256 + threadIdx.x;
    int n = idx >> 5, k = idx & 31;
    __nv_bfloat16 h, l; bf16split(W1[(size_t)k * 1024 + n], h, l);
    g_B1t_hi[idx] = h; g_B1t_lo[idx] = l;
}
__global__ void init_b1c(const float* __restrict__ W1) {
    int idx = blockIdx.x * 256 + threadIdx.x;
    int n = idx >> 7, k = idx & 127;
    __nv_bfloat16 h, l; bf16split(W1[(size_t)(33 + k) * 1024 + n], h, l);
    g_B1c_hi[idx] = h; g_B1c_lo[idx] = l;
}
__global__ void init_b2(const float* __restrict__ W2) {
    int idx = blockIdx.x * 256 + threadIdx.x;
    int n = idx >> 9, k = idx & 511;
    __nv_bfloat16 h, l; bf16split(W2[(size_t)k * 1024 + n], h, l);
    g_B2_hi[idx] = h; g_B2_lo[idx] = l;
}
__global__ void init_w3t(const float* __restrict__ W3) {
    int idx = blockIdx.x * 256 + threadIdx.x;
    int n = idx >> 9, k = idx & 511;
    __nv_bfloat16 h, l; bf16split(W3[(size_t)k * DDIM + n], h, l);
    g_W3t_hi[idx] = h; g_W3t_lo[idx] = l;
}
__global__ void init_ctx(const float* __restrict__ context) {
    int idx = blockIdx.x * 256 + threadIdx.x;
    __nv_bfloat16 h, l; bf16split(context[idx], h, l);
    g_ctx_hi[idx] = h; g_ctx_lo[idx] = l;
}
__global__ void init_theta(const float* __restrict__ theta0) {
    int idx = blockIdx.x * 256 + threadIdx.x;
    g_theta2[0][idx] = theta0[idx];
    if (blockIdx.x == 0 && threadIdx.x < 128) g_h1flag[threadIdx.x] = 0;
}

// ---------------- smem layout ----------------
#define ROWE  72
#define TILE_B (128 * ROWE * 2)
#define OFF_AH 0
#define OFF_AL (TILE_B)
#define OFF_BH (2 * TILE_B)
#define OFF_BL (3 * TILE_B)
#define STAGE_B (4 * TILE_B)            // 73728
#define W3_OFF  (3 * STAGE_B)           // 221184
#define W3_ROWB (72 * 2)
#define W3_PREC (32 * W3_ROWB)          // 4608
#define GLU_SMEM (W3_OFF + 2 * W3_PREC) // 230400
#define GLO  (128 * ROWE * 2)
// producer region aliases stage-2 (used only before consumer issues chunk 2)
#define R2 40
#define A1P (128 * R2 * 2)               // 10240
#define P_OFF   (2 * STAGE_B)            // 147456
#define PB1_OFF (P_OFF + 2 * A1P)        // B1t hi/lo after A1 hi/lo

// ================= C0 build (once per call) =================
__global__ __launch_bounds__(512)
void c0_build(const float* __restrict__ b1) {
    extern __shared__ char smem[];
    const uint32_t sb = smem_u32(smem);
    const int tid  = threadIdx.x;
    const int lane = tid & 31, wid = tid >> 5;
    const int wm = wid & 3, wn = wid >> 2;
    const int bm = blockIdx.y * 128, bn = blockIdx.x * 64;

    float acc[2][4][4];
#pragma unroll
    for (int i = 0; i < 2; ++i)
#pragma unroll
        for (int j = 0; j < 4; ++j)
#pragma unroll
            for (int q = 0; q < 4; ++q) acc[i][j][q] = 0.0f;

    auto issue = [&](int c) {
        const int kc = c * 64;
        const uint32_t st = sb + (uint32_t)((c % 3) * STAGE_B);
#pragma unroll
        for (int p = 0; p < 2; ++p) {
            int slot = p * 512 + tid;
            int row = slot >> 3, cc = slot & 7;
            uint32_t so = (uint32_t)(row * ROWE + cc * 8) * 2;
            cpasync16(st + OFF_AH + so, g_ctx_hi + (size_t)(bm + row) * 128 + kc + cc * 8);
            cpasync16(st + OFF_AL + so, g_ctx_lo + (size_t)(bm + row) * 128 + kc + cc * 8);
            int brow = (row < 64) ? (bn + row) : (448 + bn + row);
            cpasync16(st + OFF_BH + so, g_B1c_hi + (size_t)brow * 128 + kc + cc * 8);
            cpasync16(st + OFF_BL + so, g_B1c_lo + (size_t)brow * 128 + kc + cc * 8);
        }
        CP_COMMIT();
    };

    const uint32_t a_off = (uint32_t)((wm * 32 + (lane & 15)) * ROWE
                                      + ((lane >> 4) << 3)) * 2;
    const uint32_t b_off = (uint32_t)((wn * 16 + ((lane >> 4) << 3) + (lane & 7)) * ROWE
                                      + (((lane >> 3) & 1) << 3)) * 2;

    issue(0); issue(1);
    for (int c = 0; c < 2; ++c) {
        if (c == 0) CP_WAIT1(); else CP_WAIT0();
        __syncthreads();
        const uint32_t st = sb + (uint32_t)((c % 3) * STAGE_B);
#pragma unroll
        for (int kk = 0; kk < 4; ++kk) {
            const uint32_t kb = (uint32_t)(kk * 16) * 2;
            uint32_t af[2][2][4];
#pragma unroll
            for (int mi = 0; mi < 2; ++mi) {
                uint32_t o = a_off + (uint32_t)(mi * 16 * ROWE) * 2 + kb;
                ldsm4(af[0][mi], st + OFF_AH + o);
                ldsm4(af[1][mi], st + OFF_AL + o);
            }
#pragma unroll
            for (int h = 0; h < 2; ++h) {
                uint32_t bh4[4], bl4[4];
                uint32_t o = b_off + (uint32_t)(h * 64 * ROWE) * 2 + kb;
                ldsm4(bh4, st + OFF_BH + o);
                ldsm4(bl4, st + OFF_BL + o);
#pragma unroll
                for (int mi = 0; mi < 2; ++mi)
#pragma unroll
                    for (int q = 0; q < 2; ++q) {
                        float* cc2 = acc[mi][h * 2 + q];
                        mma16816(cc2, af[0][mi], &bh4[q * 2]);
                        mma16816(cc2, af[0][mi], &bl4[q * 2]);
                        mma16816(cc2, af[1][mi], &bh4[q * 2]);
                    }
            }
        }
        __syncthreads();
    }

    const int r0 = bm + wm * 32 + (lane >> 2);
    const int cb = wn * 16 + (lane & 3) * 2;
#pragma unroll
    for (int mi = 0; mi < 2; ++mi)
#pragma unroll
        for (int q = 0; q < 2; ++q) {
            int gcol = bn + cb + q * 8;
            float bia0 = b1[gcol],       bia1 = b1[gcol + 1];
            float bib0 = b1[512 + gcol], bib1 = b1[512 + gcol + 1];
            const float* ca  = acc[mi][q];
            const float* cbv = acc[mi][2 + q];
            int ra = r0 + mi * 16;
            *(float2*)(g_C0 + (size_t)ra * 1024 + gcol)
                = make_float2(ca[0] + bia0, ca[1] + bia1);
            *(float2*)(g_C0 + (size_t)ra * 1024 + 512 + gcol)
                = make_float2(cbv[0] + bib0, cbv[1] + bib1);
            *(float2*)(g_C0 + (size_t)(ra + 8) * 1024 + gcol)
                = make_float2(ca[2] + bia0, ca[3] + bia1);
            *(float2*)(g_C0 + (size_t)(ra + 8) * 1024 + 512 + gcol)
                = make_float2(cbv[2] + bib0, cbv[3] + bib1);
        }
}

// ================= fused eval kernel: grid 128, each CTA produces then consumes ====
__global__ __launch_bounds__(512)
void eval_pc(const float* __restrict__ W1, const float* __restrict__ b2,
             const float* __restrict__ b3,
             int it, float tval, float dt, int s_prev, int rd, int wr) {
    extern __shared__ char smem[];
    const uint32_t sb = smem_u32(smem);
    const int tid  = threadIdx.x;
    const int lane = tid & 31, wid = tid >> 5;
    const int wm = wid & 3, wn = wid >> 2;
    const int bnI = blockIdx.x & 7, bm16 = blockIdx.x >> 3;
    const int bn = bnI * 64, bm = bm16 * 128;
    const int target = it + 1;

    // ============ PRODUCER PHASE: layer-1 (K=32) + inline RK4 ============
    {
        const float* w132 = W1 + (size_t)32 * 1024;
        // B1t loads (128 out-rows x 32 k, hi+lo) into producer region
#pragma unroll
        for (int p = 0; p < 2; ++p) {
            int slot = p * 512 + tid;
            int prec = slot >> 9;
            int s2 = slot & 511;
            int row = s2 >> 2, cc = s2 & 3;
            uint32_t so = (uint32_t)(PB1_OFF + prec * A1P + (row * R2 + cc * 8) * 2);
            int brow = (row < 64) ? (bn + row) : (448 + bn + row);
            const __nv_bfloat16* g = (prec ? g_B1t_lo : g_B1t_hi) + (size_t)brow * 32 + cc * 8;
            cpasync16(sb + so, g);
        }
        CP_COMMIT();

        // RK4 arg build -> A1 smem (+ state update by bnI==0)
        {
            int r = tid >> 2, c0 = (tid & 3) * 8;
            size_t base = (size_t)(bm + r) * DDIM + c0;
            float th[8], kv[8], ks[8], arg[8];
            *(float4*)&th[0] = *(const float4*)&g_theta2[rd][base];
            *(float4*)&th[4] = *(const float4*)&g_theta2[rd][base + 4];
            if (it > 0) {
#pragma unroll
                for (int j = 0; j < 8; ++j) kv[j] = b3[c0 + j];
#pragma unroll
                for (int b = 0; b < 8; ++b) {
                    float4 v0 = *(const float4*)&g_kpart[(size_t)b * NELEM + base];
                    float4 v1 = *(const float4*)&g_kpart[(size_t)b * NELEM + base + 4];
                    kv[0] += v0.x; kv[1] += v0.y; kv[2] += v0.z; kv[3] += v0.w;
                    kv[4] += v1.x; kv[5] += v1.y; kv[6] += v1.z; kv[7] += v1.w;
                }
                if (s_prev >= 1) {
                    *(float4*)&ks[0] = *(const float4*)&g_ksum2[rd][base];
                    *(float4*)&ks[4] = *(const float4*)&g_ksum2[rd][base + 4];
                }
#pragma unroll
                for (int j = 0; j < 8; ++j) {
                    if (s_prev == 0 || s_prev == 1) arg[j] = th[j] + 0.5f * dt * kv[j];
                    else if (s_prev == 2)           arg[j] = th[j] + dt * kv[j];
                    else                            arg[j] = th[j] + (dt / 6.0f) * (ks[j] + kv[j]);
                }
                if (bnI == 0) {
                    float ksw[8], thw[8];
#pragma unroll
                    for (int j = 0; j < 8; ++j) {
                        if (s_prev == 0)      { ksw[j] = kv[j];                thw[j] = th[j]; }
                        else if (s_prev <= 2) { ksw[j] = ks[j] + 2.0f * kv[j]; thw[j] = th[j]; }
                        else                  { ksw[j] = ks[j] + kv[j];        thw[j] = arg[j]; }
                    }
                    *(float4*)&g_ksum2[wr][base]      = *(float4*)&ksw[0];
                    *(float4*)&g_ksum2[wr][base + 4]  = *(float4*)&ksw[4];
                    *(float4*)&g_theta2[wr][base]     = *(float4*)&thw[0];
                    *(float4*)&g_theta2[wr][base + 4] = *(float4*)&thw[4];
                }
            } else {
#pragma unroll
                for (int j = 0; j < 8; ++j) arg[j] = th[j];
            }
            uint32_t ao = (uint32_t)(P_OFF + (r * R2 + c0) * 2);
#pragma unroll
            for (int j = 0; j < 4; ++j) {
                __nv_bfloat16 h0, l0, h1, l1;
                bf16split(arg[2 * j],     h0, l0);
                bf16split(arg[2 * j + 1], h1, l1);
                *(__nv_bfloat162*)(smem + ao + j * 4)       = __nv_bfloat162(h0, h1);
                *(__nv_bfloat162*)(smem + A1P + ao + j * 4) = __nv_bfloat162(l0, l1);
            }
        }
        CP_WAIT0();
        __syncthreads();

        // K=32 mainloop
        float acc[2][4][4];
#pragma unroll
        for (int i = 0; i < 2; ++i)
#pragma unroll
            for (int j = 0; j < 4; ++j)
#pragma unroll
                for (int q = 0; q < 4; ++q) acc[i][j][q] = 0.0f;

        const uint32_t a_off = (uint32_t)(P_OFF) + (uint32_t)((wm * 32 + (lane & 15)) * R2
                                          + ((lane >> 4) << 3)) * 2;
        const uint32_t b_off = (uint32_t)(PB1_OFF) + (uint32_t)((wn * 16 + ((lane >> 4) << 3) + (lane & 7)) * R2
                                          + (((lane >> 3) & 1) << 3)) * 2;
#pragma unroll
        for (int kk = 0; kk < 2; ++kk) {
            const uint32_t kb = (uint32_t)(kk * 16) * 2;
            uint32_t af[2][2][4];
#pragma unroll
            for (int mi = 0; mi < 2; ++mi) {
                uint32_t o = a_off + (uint32_t)(mi * 16 * R2) * 2 + kb;
                ldsm4(af[0][mi], sb + o);
                ldsm4(af[1][mi], sb + A1P + o);
            }
#pragma unroll
            for (int h = 0; h < 2; ++h) {
                uint32_t bh4[4], bl4[4];
                uint32_t o = b_off + (uint32_t)(h * 64 * R2) * 2 + kb;
                ldsm4(bh4, sb + o);
                ldsm4(bl4, sb + A1P + o);
#pragma unroll
                for (int mi = 0; mi < 2; ++mi)
#pragma unroll
                    for (int q = 0; q < 2; ++q) {
                        float* cc2 = acc[mi][h * 2 + q];
                        mma16816(cc2, af[0][mi], &bh4[q * 2]);
                        mma16816(cc2, af[0][mi], &bl4[q * 2]);
                        mma16816(cc2, af[1][mi], &bh4[q * 2]);
                    }
            }
        }

        // epilogue: + C0 + t*W1[32], GLU, write h1 hi/lo
        const int r0 = bm + wm * 32 + (lane >> 2);
        const int cb = wn * 16 + (lane & 3) * 2;
#pragma unroll
        for (int mi = 0; mi < 2; ++mi)
#pragma unroll
            for (int q = 0; q < 2; ++q) {
                int gcol = bn + cb + q * 8;
                int ra = r0 + mi * 16;
                float wa0 = tval * w132[gcol],       wa1 = tval * w132[gcol + 1];
                float wb0 = tval * w132[512 + gcol], wb1 = tval * w132[512 + gcol + 1];
                float2 c0a0 = *(const float2*)&g_C0[(size_t)ra * 1024 + gcol];
                float2 c0b0 = *(const float2*)&g_C0[(size_t)ra * 1024 + 512 + gcol];
                float2 c0a1 = *(const float2*)&g_C0[(size_t)(ra + 8) * 1024 + gcol];
                float2 c0b1 = *(const float2*)&g_C0[(size_t)(ra + 8) * 1024 + 512 + gcol];
                const float* ca  = acc[mi][q];
                const float* cbv = acc[mi][2 + q];
                float g00 = (ca[0] + c0a0.x + wa0) / (1.0f + __expf(-(cbv[0] + c0b0.x + wb0)));
                float g01 = (ca[1] + c0a0.y + wa1) / (1.0f + __expf(-(cbv[1] + c0b0.y + wb1)));
                float g10 = (ca[2] + c0a1.x + wa0) / (1.0f + __expf(-(cbv[2] + c0b1.x + wb0)));
                float g11 = (ca[3] + c0a1.y + wa1) / (1.0f + __expf(-(cbv[3] + c0b1.y + wb1)));
                size_t o0 = (size_t)ra * HID + gcol;
                size_t o1 = (size_t)(ra + 8) * HID + gcol;
                __nv_bfloat16 h0, l0, h1, l1;
                bf16split(g00, h0, l0); bf16split(g01, h1, l1);
                *(__nv_bfloat162*)(g_h1_hi + o0) = __nv_bfloat162(h0, h1);
                *(__nv_bfloat162*)(g_h1_lo + o0) = __nv_bfloat162(l0, l1);
                bf16split(g10, h0, l0); bf16split(g11, h1, l1);
                *(__nv_bfloat162*)(g_h1_hi + o1) = __nv_bfloat162(h0, h1);
                *(__nv_bfloat162*)(g_h1_lo + o1) = __nv_bfloat162(l0, l1);
            }

        __threadfence();
        __syncthreads();
        if (tid == 0) flag_release(&g_h1flag[bm16 * 8 + bnI], target);
    }

    // ============ CONSUMER PHASE: layer-2 GLU + k3 partial ============
    float acc[2][4][4];
#pragma unroll
    for (int i = 0; i < 2; ++i)
#pragma unroll
        for (int j = 0; j < 4; ++j)
#pragma unroll
            for (int q = 0; q < 4; ++q) acc[i][j][q] = 0.0f;

    auto issue = [&](int c) {
        const int kc = c * 64;
        const uint32_t st = sb + (uint32_t)((c % 3) * STAGE_B);
        // B2 part first (flag-independent; in flight while we poll)
#pragma unroll
        for (int p = 0; p < 2; ++p) {
            int slot = p * 512 + tid;
            int row = slot >> 3, cc = slot & 7;
            uint32_t so = (uint32_t)(row * ROWE + cc * 8) * 2;
            int brow = (row < 64) ? (bn + row) : (448 + bn + row);
            cpasync16(st + OFF_BH + so, g_B2_hi + (size_t)brow * HID + kc + cc * 8);
            cpasync16(st + OFF_BL + so, g_B2_lo + (size_t)brow * HID + kc + cc * 8);
        }
        if (c == 0) {
            int prec = tid >> 8, s2 = tid & 255;
            int row = s2 >> 3, cc = s2 & 7;
            uint32_t so = (uint32_t)(W3_OFF + prec * W3_PREC + row * W3_ROWB + cc * 16);
            const __nv_bfloat16* g = (prec ? g_W3t_lo : g_W3t_hi)
                                     + (size_t)row * HID + bn + cc * 8;
            cpasync16(sb + so, g);
        }
        // wait for producer of h1 chunk c
        {
            const int* fp = &g_h1flag[bm16 * 8 + c];
            while (flag_acquire(fp) < target) __nanosleep(40);
        }
#pragma unroll
        for (int p = 0; p < 2; ++p) {
            int slot = p * 512 + tid;
            int row = slot >> 3, cc = slot & 7;
            uint32_t so = (uint32_t)(row * ROWE + cc * 8) * 2;
            cpasync16(st + OFF_AH + so, g_h1_hi + (size_t)(bm + row) * HID + kc + cc * 8);
            cpasync16(st + OFF_AL + so, g_h1_lo + (size_t)(bm + row) * HID + kc + cc * 8);
        }
        CP_COMMIT();
    };

    const uint32_t a_off = (uint32_t)((wm * 32 + (lane & 15)) * ROWE
                                      + ((lane >> 4) << 3)) * 2;
    const uint32_t b_off = (uint32_t)((wn * 16 + ((lane >> 4) << 3) + (lane & 7)) * ROWE
                                      + (((lane >> 3) & 1) << 3)) * 2;
    const int cb = wn * 16 + (lane & 3) * 2;

    issue(0); issue(1);

    for (int c = 0; c < 8; ++c) {
        if (c + 1 < 8) CP_WAIT1(); else CP_WAIT0();
        __syncthreads();
        if (c + 2 < 8) issue(c + 2);

        const uint32_t st = sb + (uint32_t)((c % 3) * STAGE_B);
#pragma unroll
        for (int kk = 0; kk < 4; ++kk) {
            const uint32_t kb = (uint32_t)(kk * 16) * 2;
            uint32_t af[2][2][4];
#pragma unroll
            for (int mi = 0; mi < 2; ++mi) {
                uint32_t o = a_off + (uint32_t)(mi * 16 * ROWE) * 2 + kb;
                ldsm4(af[0][mi], st + OFF_AH + o);
                ldsm4(af[1][mi], st + OFF_AL + o);
            }
#pragma unroll
            for (int h = 0; h < 2; ++h) {
                uint32_t bh4[4], bl4[4];
                uint32_t o = b_off + (uint32_t)(h * 64 * ROWE) * 2 + kb;
                ldsm4(bh4, st + OFF_BH + o);
                ldsm4(bl4, st + OFF_BL + o);
#pragma unroll
                for (int mi = 0; mi < 2; ++mi)
#pragma unroll
                    for (int q = 0; q < 2; ++q) {
                        float* cc2 = acc[mi][h * 2 + q];
                        mma16816(cc2, af[0][mi], &bh4[q * 2]);
                        mma16816(cc2, af[0][mi], &bl4[q * 2]);
                        mma16816(cc2, af[1][mi], &bh4[q * 2]);
                    }
            }
        }
    }

    // tail: g = GLU(acc+b2) -> smem stage0; kpart = g @ W3slice^T
    __syncthreads();
    {
#pragma unroll
        for (int mi = 0; mi < 2; ++mi)
#pragma unroll
            for (int q = 0; q < 2; ++q) {
                int gcol = bn + cb + q * 8;
                float bia0 = b2[gcol],       bia1 = b2[gcol + 1];
                float bib0 = b2[512 + gcol], bib1 = b2[512 + gcol + 1];
                const float* ca  = acc[mi][q];
                const float* cbv = acc[mi][2 + q];
                float g00 = (ca[0] + bia0) / (1.0f + __expf(-(cbv[0] + bib0)));
                float g01 = (ca[1] + bia1) / (1.0f + __expf(-(cbv[1] + bib1)));
                float g10 = (ca[2] + bia0) / (1.0f + __expf(-(cbv[2] + bib0)));
                float g11 = (ca[3] + bia1) / (1.0f + __expf(-(cbv[3] + bib1)));
                int lr = wm * 32 + (lane >> 2) + mi * 16;
                int lc = cb + q * 8;
                __nv_bfloat16 h0, l0, h1, l1;
                uint32_t o0 = (uint32_t)(lr * ROWE + lc) * 2;
                bf16split(g00, h0, l0); bf16split(g01, h1, l1);
                *(__nv_bfloat162*)(smem + o0)       = __nv_bfloat162(h0, h1);
                *(__nv_bfloat162*)(smem + GLO + o0) = __nv_bfloat162(l0, l1);
                uint32_t o1 = (uint32_t)((lr + 8) * ROWE + lc) * 2;
                bf16split(g10, h0, l0); bf16split(g11, h1, l1);
                *(__nv_bfloat162*)(smem + o1)       = __nv_bfloat162(h0, h1);
                *(__nv_bfloat162*)(smem + GLO + o1) = __nv_bfloat162(l0, l1);
            }
        __syncthreads();

        if (wid < 8) {
            float accs[4][4];
#pragma unroll
            for (int i = 0; i < 4; ++i)
#pragma unroll
                for (int j = 0; j < 4; ++j) accs[i][j] = 0.0f;

            const uint32_t a_b = sb + (uint32_t)((wid * 16 + (lane & 15)) * ROWE
                                                 + ((lane >> 4) << 3)) * 2;
            const uint32_t w_b = sb + W3_OFF
                + (uint32_t)(((lane >> 4) << 3) + (lane & 7)) * W3_ROWB
                + (uint32_t)((((lane >> 3) & 1) << 3)) * 2;
#pragma unroll
            for (int kk = 0; kk < 4; ++kk) {
                uint32_t ah[4], al[4];
                ldsm4(ah, a_b + kk * 32);
                ldsm4(al, a_b + GLO + kk * 32);
#pragma unroll
                for (int p = 0; p < 2; ++p) {
                    uint32_t bo = w_b + (uint32_t)(p * 16 * W3_ROWB) + kk * 32;
                    uint32_t bh4[4], bl4[4];
                    ldsm4(bh4, bo);
                    ldsm4(bl4, bo + W3_PREC);
#pragma unroll
                    for (int q = 0; q < 2; ++q) {
                        float* cc2 = accs[p * 2 + q];
                        mma16816(cc2, ah, &bh4[q * 2]);
                        mma16816(cc2, ah, &bl4[q * 2]);
                        mma16816(cc2, al, &bh4[q * 2]);
                    }
                }
            }
            float* kp = g_kpart + (size_t)bnI * NELEM;
#pragma unroll
            for (int nt = 0; nt < 4; ++nt)
#pragma unroll
                for (int half = 0; half < 2; ++half) {
                    int lr = wid * 16 + (lane >> 2) + half * 8;
                    int col = nt * 8 + (lane & 3) * 2;
                    *(float2*)(kp + (size_t)(bm + lr) * DDIM + col)
                        = make_float2(accs[nt][half * 2], accs[nt][half * 2 + 1]);
                }
        }
    }
}

// ---------------- final RK4 combine ----------------
__global__ __launch_bounds__(256)
void final_update(const float* __restrict__ b3, float dt, float* __restrict__ out) {
    int idx = blockIdx.x * 256 + threadIdx.x;
    int c = idx & 31;
    float kv = b3[c];
#pragma unroll
    for (int b = 0; b < 8; ++b)
        kv += g_kpart[(size_t)b * NELEM + idx];
    out[idx] = g_theta2[1][idx] + (dt / 6.0f) * (g_ksum2[1][idx] + kv);
}

// ---------------- host launcher ----------------
extern "C" void kernel_launch(void* const* d_in, const int* in_sizes, int n_in,
                              void* d_out, int out_size) {
    const float* theta0  = (const float*)d_in[0];
    const float* context = (const float*)d_in[1];
    const float* W1      = (const float*)d_in[2];
    const float* b1      = (const float*)d_in[3];
    const float* W2      = (const float*)d_in[4];
    const float* b2      = (const float*)d_in[5];
    const float* W3      = (const float*)d_in[6];
    const float* b3      = (const float*)d_in[7];
    float* out = (float*)d_out;

    cudaFuncSetAttribute(c0_build, cudaFuncAttributeMaxDynamicSharedMemorySize, GLU_SMEM);
    cudaFuncSetAttribute(eval_pc,  cudaFuncAttributeMaxDynamicSharedMemorySize, GLU_SMEM);

    init_b1t<<<128, 256>>>(W1);
    init_b1c<<<512, 256>>>(W1);
    init_b2<<<2048, 256>>>(W2);
    init_w3t<<<64, 256>>>(W3);
    init_ctx<<<1024, 256>>>(context);
    init_theta<<<256, 256>>>(theta0);

    const float dt = 1.0f / NSTEPS;
    dim3 cgrid(8, 16);
    c0_build<<<cgrid, 512, GLU_SMEM>>>(b1);

    for (int it = 0; it < NSTEPS * 4; ++it) {
        int s = it & 3;
        float tval = (float)(it >> 2) * dt + ((s == 0) ? 0.0f : (s < 3 ? 0.5f * dt : dt));
        int s_prev = (it - 1) & 3;
        int rd = (it == 0) ? 0 : ((it - 1) & 1);
        int wr = it & 1;
        eval_pc<<<128, 512, GLU_SMEM>>>(W1, b2, b3, it, tval, dt, s_prev, rd, wr);
    }
    final_update<<<256, 256>>>(b3, dt, out);
}

// round 12
// speedup vs baseline: 1.1208x; 1.1208x over previous
#include <cuda_runtime.h>
#include <cuda_bf16.h>
#include <math.h>
#include <stdint.h>

// ---------------- problem constants ----------------
#define BATCH  2048
#define DDIM   32
#define HID    512
#define NSTEPS 16
#define NELEM  (BATCH * DDIM)

// ---------------- device scratch ----------------
__device__ __align__(16) __nv_bfloat16 g_h1_hi[BATCH * HID];
__device__ __align__(16) __nv_bfloat16 g_h1_lo[BATCH * HID];
__device__ __align__(16) float         g_theta2[2][NELEM];
__device__ __align__(16) float         g_ksum2 [2][NELEM];
__device__ __align__(16) float         g_kpart[8 * NELEM];
__device__ __align__(16) __nv_bfloat16 g_B1t_hi[1024 * 32];
__device__ __align__(16) __nv_bfloat16 g_B1t_lo[1024 * 32];
__device__ __align__(16) __nv_bfloat16 g_B1c_hi[1024 * 128];
__device__ __align__(16) __nv_bfloat16 g_B1c_lo[1024 * 128];
__device__ __align__(16) __nv_bfloat16 g_B2_hi[1024 * HID];
__device__ __align__(16) __nv_bfloat16 g_B2_lo[1024 * HID];
__device__ __align__(16) __nv_bfloat16 g_W3t_hi[DDIM * HID];
__device__ __align__(16) __nv_bfloat16 g_W3t_lo[DDIM * HID];
__device__ __align__(16) __nv_bfloat16 g_ctx_hi[BATCH * 128];
__device__ __align__(16) __nv_bfloat16 g_ctx_lo[BATCH * 128];
__device__ __align__(16) float         g_C0[BATCH * 1024];    // ctx@W1c + b1 (fp32)
__device__ int g_h1flag[16 * 8];                              // producer -> consumer
__device__ int g_kpflag[16 * 8];                              // consumer -> next producer

// ---------------- PTX helpers (compute_100-safe) ----------------
__device__ __forceinline__ uint32_t smem_u32(const void* p) {
    uint32_t a;
    asm("{ .reg .u64 t; cvta.to.shared.u64 t, %1; cvt.u32.u64 %0, t; }"
        : "=r"(a) : "l"(p));
    return a;
}
__device__ __forceinline__ void cpasync16(uint32_t saddr, const void* g) {
    asm volatile("cp.async.cg.shared.global [%0], [%1], 16;"
                 :: "r"(saddr), "l"(g) : "memory");
}
#define CP_COMMIT() asm volatile("cp.async.commit_group;" ::: "memory")
#define CP_WAIT0()  asm volatile("cp.async.wait_group 0;" ::: "memory")
#define CP_WAIT1()  asm volatile("cp.async.wait_group 1;" ::: "memory")

__device__ __forceinline__ void ldsm4(uint32_t* r, uint32_t addr) {
    asm volatile("ldmatrix.sync.aligned.m8n8.x4.shared.b16 {%0,%1,%2,%3}, [%4];"
                 : "=r"(r[0]), "=r"(r[1]), "=r"(r[2]), "=r"(r[3]) : "r"(addr));
}
__device__ __forceinline__ void mma16816(float* c, const uint32_t* a, const uint32_t* b) {
    asm volatile("mma.sync.aligned.m16n8k16.row.col.f32.bf16.bf16.f32 "
                 "{%0,%1,%2,%3}, {%4,%5,%6,%7}, {%8,%9}, {%0,%1,%2,%3};"
                 : "+f"(c[0]), "+f"(c[1]), "+f"(c[2]), "+f"(c[3])
                 : "r"(a[0]), "r"(a[1]), "r"(a[2]), "r"(a[3]),
                   "r"(b[0]), "r"(b[1]));
}
__device__ __forceinline__ void bf16split(float v, __nv_bfloat16& h, __nv_bfloat16& l) {
    h = __float2bfloat16(v);
    l = __float2bfloat16(v - __bfloat162float(h));
}
__device__ __forceinline__ void flag_release(int* p, int v) {
    asm volatile("st.release.gpu.global.b32 [%0], %1;" :: "l"(p), "r"(v) : "memory");
}
__device__ __forceinline__ int flag_acquire(const int* p) {
    int v;
    asm volatile("ld.acquire.gpu.global.b32 %0, [%1];" : "=r"(v) : "l"(p) : "memory");
    return v;
}
__device__ __forceinline__ void wait_flag(const int* p, int target) {
    while (flag_acquire(p) < target) __nanosleep(40);
}

// ---------------- merged init kernel ----------------
// segments: [B2: 524288][ctx: 262144][b1c: 131072][theta: 65536][b1t: 32768][w3t: 16384]
#define SEG_B2   524288
#define SEG_CTX  (SEG_B2 + 262144)        // 786432
#define SEG_B1C  (SEG_CTX + 131072)       // 917504
#define SEG_TH   (SEG_B1C + 65536)        // 983040
#define SEG_B1T  (SEG_TH + 32768)         // 1015808
#define SEG_W3   (SEG_B1T + 16384)        // 1032192
#define INIT_TOT SEG_W3

__global__ void init_all(const float* __restrict__ W1, const float* __restrict__ W2,
                         const float* __restrict__ W3, const float* __restrict__ context,
                         const float* __restrict__ theta0) {
    int idx = blockIdx.x * 256 + threadIdx.x;
    if (idx < 256) { if (idx < 128) g_h1flag[idx] = 0; else g_kpflag[idx - 128] = 0; }
    if (idx >= INIT_TOT) return;
    __nv_bfloat16 h, l;
    if (idx < SEG_B2) {
        int n = idx >> 9, k = idx & 511;
        bf16split(W2[(size_t)k * 1024 + n], h, l);
        g_B2_hi[idx] = h; g_B2_lo[idx] = l;
    } else if (idx < SEG_CTX) {
        int i = idx - SEG_B2;
        bf16split(context[i], h, l);
        g_ctx_hi[i] = h; g_ctx_lo[i] = l;
    } else if (idx < SEG_B1C) {
        int i = idx - SEG_CTX;
        int n = i >> 7, k = i & 127;
        bf16split(W1[(size_t)(33 + k) * 1024 + n], h, l);
        g_B1c_hi[i] = h; g_B1c_lo[i] = l;
    } else if (idx < SEG_TH) {
        int i = idx - SEG_B1C;
        g_theta2[0][i] = theta0[i];
    } else if (idx < SEG_B1T) {
        int i = idx - SEG_TH;
        int n = i >> 5, k = i & 31;
        bf16split(W1[(size_t)k * 1024 + n], h, l);
        g_B1t_hi[i] = h; g_B1t_lo[i] = l;
    } else {
        int i = idx - SEG_B1T;
        int n = i >> 9, k = i & 511;
        bf16split(W3[(size_t)k * DDIM + n], h, l);
        g_W3t_hi[i] = h; g_W3t_lo[i] = l;
    }
}

// ---------------- smem layout ----------------
#define ROWE  72
#define TILE_B (128 * ROWE * 2)
#define OFF_AH 0
#define OFF_AL (TILE_B)
#define OFF_BH (2 * TILE_B)
#define OFF_BL (3 * TILE_B)
#define STAGE_B (4 * TILE_B)            // 73728
#define W3_OFF  (3 * STAGE_B)           // 221184
#define W3_ROWB (72 * 2)
#define W3_PREC (32 * W3_ROWB)          // 4608
#define GLU_SMEM (W3_OFF + 2 * W3_PREC) // 230400
#define GLO  (128 * ROWE * 2)
// producer region aliases consumer stage-2
#define R2 40
#define A1P (128 * R2 * 2)               // 10240
#define P_OFF   (2 * STAGE_B)            // 147456
#define PB1_OFF (P_OFF + 2 * A1P)

// ================= C0 build (once per call) =================
__global__ __launch_bounds__(512)
void c0_build(const float* __restrict__ b1) {
    extern __shared__ char smem[];
    const uint32_t sb = smem_u32(smem);
    const int tid  = threadIdx.x;
    const int lane = tid & 31, wid = tid >> 5;
    const int wm = wid & 3, wn = wid >> 2;
    const int bm = blockIdx.y * 128, bn = blockIdx.x * 64;

    float acc[2][4][4];
#pragma unroll
    for (int i = 0; i < 2; ++i)
#pragma unroll
        for (int j = 0; j < 4; ++j)
#pragma unroll
            for (int q = 0; q < 4; ++q) acc[i][j][q] = 0.0f;

    auto issue = [&](int c) {
        const int kc = c * 64;
        const uint32_t st = sb + (uint32_t)((c % 3) * STAGE_B);
#pragma unroll
        for (int p = 0; p < 2; ++p) {
            int slot = p * 512 + tid;
            int row = slot >> 3, cc = slot & 7;
            uint32_t so = (uint32_t)(row * ROWE + cc * 8) * 2;
            cpasync16(st + OFF_AH + so, g_ctx_hi + (size_t)(bm + row) * 128 + kc + cc * 8);
            cpasync16(st + OFF_AL + so, g_ctx_lo + (size_t)(bm + row) * 128 + kc + cc * 8);
            int brow = (row < 64) ? (bn + row) : (448 + bn + row);
            cpasync16(st + OFF_BH + so, g_B1c_hi + (size_t)brow * 128 + kc + cc * 8);
            cpasync16(st + OFF_BL + so, g_B1c_lo + (size_t)brow * 128 + kc + cc * 8);
        }
        CP_COMMIT();
    };

    const uint32_t a_off = (uint32_t)((wm * 32 + (lane & 15)) * ROWE
                                      + ((lane >> 4) << 3)) * 2;
    const uint32_t b_off = (uint32_t)((wn * 16 + ((lane >> 4) << 3) + (lane & 7)) * ROWE
                                      + (((lane >> 3) & 1) << 3)) * 2;

    issue(0); issue(1);
    for (int c = 0; c < 2; ++c) {
        if (c == 0) CP_WAIT1(); else CP_WAIT0();
        __syncthreads();
        const uint32_t st = sb + (uint32_t)((c % 3) * STAGE_B);
#pragma unroll
        for (int kk = 0; kk < 4; ++kk) {
            const uint32_t kb = (uint32_t)(kk * 16) * 2;
            uint32_t af[2][2][4];
#pragma unroll
            for (int mi = 0; mi < 2; ++mi) {
                uint32_t o = a_off + (uint32_t)(mi * 16 * ROWE) * 2 + kb;
                ldsm4(af[0][mi], st + OFF_AH + o);
                ldsm4(af[1][mi], st + OFF_AL + o);
            }
#pragma unroll
            for (int h = 0; h < 2; ++h) {
                uint32_t bh4[4], bl4[4];
                uint32_t o = b_off + (uint32_t)(h * 64 * ROWE) * 2 + kb;
                ldsm4(bh4, st + OFF_BH + o);
                ldsm4(bl4, st + OFF_BL + o);
#pragma unroll
                for (int mi = 0; mi < 2; ++mi)
#pragma unroll
                    for (int q = 0; q < 2; ++q) {
                        float* cc2 = acc[mi][h * 2 + q];
                        mma16816(cc2, af[0][mi], &bh4[q * 2]);
                        mma16816(cc2, af[0][mi], &bl4[q * 2]);
                        mma16816(cc2, af[1][mi], &bh4[q * 2]);
                    }
            }
        }
        __syncthreads();
    }

    const int r0 = bm + wm * 32 + (lane >> 2);
    const int cb = wn * 16 + (lane & 3) * 2;
#pragma unroll
    for (int mi = 0; mi < 2; ++mi)
#pragma unroll
        for (int q = 0; q < 2; ++q) {
            int gcol = bn + cb + q * 8;
            float bia0 = b1[gcol],       bia1 = b1[gcol + 1];
            float bib0 = b1[512 + gcol], bib1 = b1[512 + gcol + 1];
            const float* ca  = acc[mi][q];
            const float* cbv = acc[mi][2 + q];
            int ra = r0 + mi * 16;
            *(float2*)(g_C0 + (size_t)ra * 1024 + gcol)
                = make_float2(ca[0] + bia0, ca[1] + bia1);
            *(float2*)(g_C0 + (size_t)ra * 1024 + 512 + gcol)
                = make_float2(cbv[0] + bib0, cbv[1] + bib1);
            *(float2*)(g_C0 + (size_t)(ra + 8) * 1024 + gcol)
                = make_float2(ca[2] + bia0, ca[3] + bia1);
            *(float2*)(g_C0 + (size_t)(ra + 8) * 1024 + 512 + gcol)
                = make_float2(cbv[2] + bib0, cbv[3] + bib1);
        }
}

// ================= persistent eval kernel: grid 128, all 64 evals =================
__global__ __launch_bounds__(512)
void persist(const float* __restrict__ W1, const float* __restrict__ b2,
             const float* __restrict__ b3, float dt) {
    extern __shared__ char smem[];
    const uint32_t sb = smem_u32(smem);
    const int tid  = threadIdx.x;
    const int lane = tid & 31, wid = tid >> 5;
    const int wm = wid & 3, wn = wid >> 2;
    const int bnI = blockIdx.x & 7, bm16 = blockIdx.x >> 3;
    const int bn = bnI * 64, bm = bm16 * 128;
    const float* w132 = W1 + (size_t)32 * 1024;

    const uint32_t a_off = (uint32_t)((wm * 32 + (lane & 15)) * ROWE
                                      + ((lane >> 4) << 3)) * 2;
    const uint32_t b_off = (uint32_t)((wn * 16 + ((lane >> 4) << 3) + (lane & 7)) * ROWE
                                      + (((lane >> 3) & 1) << 3)) * 2;
    const uint32_t a1_off = (uint32_t)(P_OFF) + (uint32_t)((wm * 32 + (lane & 15)) * R2
                                      + ((lane >> 4) << 3)) * 2;
    const uint32_t b1_off = (uint32_t)(PB1_OFF) + (uint32_t)((wn * 16 + ((lane >> 4) << 3)
                                      + (lane & 7)) * R2 + (((lane >> 3) & 1) << 3)) * 2;
    const int cb = wn * 16 + (lane & 3) * 2;

#pragma unroll 1
    for (int it = 0; it < NSTEPS * 4; ++it) {
        const int s = it & 3;
        const float tval = (float)(it >> 2) * dt
                         + ((s == 0) ? 0.0f : (s < 3 ? 0.5f * dt : dt));
        const int s_prev = (it - 1) & 3;
        const int rd = (it == 0) ? 0 : ((it - 1) & 1);
        const int wr = it & 1;
        const int target = it + 1;

        // ============ PRODUCER PHASE ============
        {
            // B1t loads into producer region (flag-independent)
#pragma unroll
            for (int p = 0; p < 2; ++p) {
                int slot = p * 512 + tid;
                int prec = slot >> 9;
                int s2 = slot & 511;
                int row = s2 >> 2, cc = s2 & 3;
                uint32_t so = (uint32_t)(PB1_OFF + prec * A1P + (row * R2 + cc * 8) * 2);
                int brow = (row < 64) ? (bn + row) : (448 + bn + row);
                const __nv_bfloat16* g = (prec ? g_B1t_lo : g_B1t_hi)
                                         + (size_t)brow * 32 + cc * 8;
                cpasync16(sb + so, g);
            }
            CP_COMMIT();

            // wait for all group consumers of it-1 (kpart ready)
            if (it > 0) {
                if (tid < 8) wait_flag(&g_kpflag[bm16 * 8 + tid], it);
                __syncthreads();
            }

            // RK4 arg build -> A1 smem (+ state update by bnI==0)
            {
                int r = tid >> 2, c0 = (tid & 3) * 8;
                size_t base = (size_t)(bm + r) * DDIM + c0;
                float th[8], kv[8], ks[8], arg[8];
                *(float4*)&th[0] = *(const float4*)&g_theta2[rd][base];
                *(float4*)&th[4] = *(const float4*)&g_theta2[rd][base + 4];
                if (it > 0) {
#pragma unroll
                    for (int j = 0; j < 8; ++j) kv[j] = b3[c0 + j];
#pragma unroll
                    for (int b = 0; b < 8; ++b) {
                        float4 v0 = *(const float4*)&g_kpart[(size_t)b * NELEM + base];
                        float4 v1 = *(const float4*)&g_kpart[(size_t)b * NELEM + base + 4];
                        kv[0] += v0.x; kv[1] += v0.y; kv[2] += v0.z; kv[3] += v0.w;
                        kv[4] += v1.x; kv[5] += v1.y; kv[6] += v1.z; kv[7] += v1.w;
                    }
                    if (s_prev >= 1) {
                        *(float4*)&ks[0] = *(const float4*)&g_ksum2[rd][base];
                        *(float4*)&ks[4] = *(const float4*)&g_ksum2[rd][base + 4];
                    }
#pragma unroll
                    for (int j = 0; j < 8; ++j) {
                        if (s_prev == 0 || s_prev == 1) arg[j] = th[j] + 0.5f * dt * kv[j];
                        else if (s_prev == 2)           arg[j] = th[j] + dt * kv[j];
                        else arg[j] = th[j] + (dt / 6.0f) * (ks[j] + kv[j]);
                    }
                    if (bnI == 0) {
                        float ksw[8], thw[8];
#pragma unroll
                        for (int j = 0; j < 8; ++j) {
                            if (s_prev == 0)      { ksw[j] = kv[j];                thw[j] = th[j]; }
                            else if (s_prev <= 2) { ksw[j] = ks[j] + 2.0f * kv[j]; thw[j] = th[j]; }
                            else                  { ksw[j] = ks[j] + kv[j];        thw[j] = arg[j]; }
                        }
                        *(float4*)&g_ksum2[wr][base]      = *(float4*)&ksw[0];
                        *(float4*)&g_ksum2[wr][base + 4]  = *(float4*)&ksw[4];
                        *(float4*)&g_theta2[wr][base]     = *(float4*)&thw[0];
                        *(float4*)&g_theta2[wr][base + 4] = *(float4*)&thw[4];
                    }
                } else {
#pragma unroll
                    for (int j = 0; j < 8; ++j) arg[j] = th[j];
                }
                uint32_t ao = (uint32_t)(P_OFF + (r * R2 + c0) * 2);
#pragma unroll
                for (int j = 0; j < 4; ++j) {
                    __nv_bfloat16 h0, l0, h1, l1;
                    bf16split(arg[2 * j],     h0, l0);
                    bf16split(arg[2 * j + 1], h1, l1);
                    *(__nv_bfloat162*)(smem + ao + j * 4)       = __nv_bfloat162(h0, h1);
                    *(__nv_bfloat162*)(smem + A1P + ao + j * 4) = __nv_bfloat162(l0, l1);
                }
            }
            CP_WAIT0();
            __syncthreads();

            // K=32 mainloop
            float acc[2][4][4];
#pragma unroll
            for (int i = 0; i < 2; ++i)
#pragma unroll
                for (int j = 0; j < 4; ++j)
#pragma unroll
                    for (int q = 0; q < 4; ++q) acc[i][j][q] = 0.0f;
#pragma unroll
            for (int kk = 0; kk < 2; ++kk) {
                const uint32_t kb = (uint32_t)(kk * 16) * 2;
                uint32_t af[2][2][4];
#pragma unroll
                for (int mi = 0; mi < 2; ++mi) {
                    uint32_t o = a1_off + (uint32_t)(mi * 16 * R2) * 2 + kb;
                    ldsm4(af[0][mi], sb + o);
                    ldsm4(af[1][mi], sb + A1P + o);
                }
#pragma unroll
                for (int h = 0; h < 2; ++h) {
                    uint32_t bh4[4], bl4[4];
                    uint32_t o = b1_off + (uint32_t)(h * 64 * R2) * 2 + kb;
                    ldsm4(bh4, sb + o);
                    ldsm4(bl4, sb + A1P + o);
#pragma unroll
                    for (int mi = 0; mi < 2; ++mi)
#pragma unroll
                        for (int q = 0; q < 2; ++q) {
                            float* cc2 = acc[mi][h * 2 + q];
                            mma16816(cc2, af[0][mi], &bh4[q * 2]);
                            mma16816(cc2, af[0][mi], &bl4[q * 2]);
                            mma16816(cc2, af[1][mi], &bh4[q * 2]);
                        }
                }
            }

            // epilogue: + C0 + t*W1[32], GLU, write h1 hi/lo
            const int r0 = bm + wm * 32 + (lane >> 2);
#pragma unroll
            for (int mi = 0; mi < 2; ++mi)
#pragma unroll
                for (int q = 0; q < 2; ++q) {
                    int gcol = bn + cb + q * 8;
                    int ra = r0 + mi * 16;
                    float wa0 = tval * w132[gcol],       wa1 = tval * w132[gcol + 1];
                    float wb0 = tval * w132[512 + gcol], wb1 = tval * w132[512 + gcol + 1];
                    float2 c0a0 = *(const float2*)&g_C0[(size_t)ra * 1024 + gcol];
                    float2 c0b0 = *(const float2*)&g_C0[(size_t)ra * 1024 + 512 + gcol];
                    float2 c0a1 = *(const float2*)&g_C0[(size_t)(ra + 8) * 1024 + gcol];
                    float2 c0b1 = *(const float2*)&g_C0[(size_t)(ra + 8) * 1024 + 512 + gcol];
                    const float* ca  = acc[mi][q];
                    const float* cbv = acc[mi][2 + q];
                    float g00 = (ca[0] + c0a0.x + wa0) / (1.0f + __expf(-(cbv[0] + c0b0.x + wb0)));
                    float g01 = (ca[1] + c0a0.y + wa1) / (1.0f + __expf(-(cbv[1] + c0b0.y + wb1)));
                    float g10 = (ca[2] + c0a1.x + wa0) / (1.0f + __expf(-(cbv[2] + c0b1.x + wb0)));
                    float g11 = (ca[3] + c0a1.y + wa1) / (1.0f + __expf(-(cbv[3] + c0b1.y + wb1)));
                    size_t o0 = (size_t)ra * HID + gcol;
                    size_t o1 = (size_t)(ra + 8) * HID + gcol;
                    __nv_bfloat16 h0, l0, h1, l1;
                    bf16split(g00, h0, l0); bf16split(g01, h1, l1);
                    *(__nv_bfloat162*)(g_h1_hi + o0) = __nv_bfloat162(h0, h1);
                    *(__nv_bfloat162*)(g_h1_lo + o0) = __nv_bfloat162(l0, l1);
                    bf16split(g10, h0, l0); bf16split(g11, h1, l1);
                    *(__nv_bfloat162*)(g_h1_hi + o1) = __nv_bfloat162(h0, h1);
                    *(__nv_bfloat162*)(g_h1_lo + o1) = __nv_bfloat162(l0, l1);
                }

            __threadfence();
            __syncthreads();
            if (tid == 0) flag_release(&g_h1flag[bm16 * 8 + bnI], target);
        }

        // ============ CONSUMER PHASE ============
        float acc[2][4][4];
#pragma unroll
        for (int i = 0; i < 2; ++i)
#pragma unroll
            for (int j = 0; j < 4; ++j)
#pragma unroll
                for (int q = 0; q < 4; ++q) acc[i][j][q] = 0.0f;

        auto issue = [&](int c) {
            const int kc = c * 64;
            const uint32_t st = sb + (uint32_t)((c % 3) * STAGE_B);
            // B2 (flag-independent)
#pragma unroll
            for (int p = 0; p < 2; ++p) {
                int slot = p * 512 + tid;
                int row = slot >> 3, cc = slot & 7;
                uint32_t so = (uint32_t)(row * ROWE + cc * 8) * 2;
                int brow = (row < 64) ? (bn + row) : (448 + bn + row);
                cpasync16(st + OFF_BH + so, g_B2_hi + (size_t)brow * HID + kc + cc * 8);
                cpasync16(st + OFF_BL + so, g_B2_lo + (size_t)brow * HID + kc + cc * 8);
            }
            if (c == 0) {
                int prec = tid >> 8, s2 = tid & 255;
                int row = s2 >> 3, cc = s2 & 7;
                uint32_t so = (uint32_t)(W3_OFF + prec * W3_PREC + row * W3_ROWB + cc * 16);
                const __nv_bfloat16* g = (prec ? g_W3t_lo : g_W3t_hi)
                                         + (size_t)row * HID + bn + cc * 8;
                cpasync16(sb + so, g);
            }
            // single-thread poll, then barrier broadcast
            if (tid == 0) wait_flag(&g_h1flag[bm16 * 8 + c], target);
            __syncthreads();
            // A (h1)
#pragma unroll
            for (int p = 0; p < 2; ++p) {
                int slot = p * 512 + tid;
                int row = slot >> 3, cc = slot & 7;
                uint32_t so = (uint32_t)(row * ROWE + cc * 8) * 2;
                cpasync16(st + OFF_AH + so, g_h1_hi + (size_t)(bm + row) * HID + kc + cc * 8);
                cpasync16(st + OFF_AL + so, g_h1_lo + (size_t)(bm + row) * HID + kc + cc * 8);
            }
            CP_COMMIT();
        };

        issue(0); issue(1);

        for (int c = 0; c < 8; ++c) {
            if (c + 1 < 8) CP_WAIT1(); else CP_WAIT0();
            __syncthreads();
            if (c + 2 < 8) issue(c + 2);

            const uint32_t st = sb + (uint32_t)((c % 3) * STAGE_B);
#pragma unroll
            for (int kk = 0; kk < 4; ++kk) {
                const uint32_t kb = (uint32_t)(kk * 16) * 2;
                uint32_t af[2][2][4];
#pragma unroll
                for (int mi = 0; mi < 2; ++mi) {
                    uint32_t o = a_off + (uint32_t)(mi * 16 * ROWE) * 2 + kb;
                    ldsm4(af[0][mi], st + OFF_AH + o);
                    ldsm4(af[1][mi], st + OFF_AL + o);
                }
#pragma unroll
                for (int h = 0; h < 2; ++h) {
                    uint32_t bh4[4], bl4[4];
                    uint32_t o = b_off + (uint32_t)(h * 64 * ROWE) * 2 + kb;
                    ldsm4(bh4, st + OFF_BH + o);
                    ldsm4(bl4, st + OFF_BL + o);
#pragma unroll
                    for (int mi = 0; mi < 2; ++mi)
#pragma unroll
                        for (int q = 0; q < 2; ++q) {
                            float* cc2 = acc[mi][h * 2 + q];
                            mma16816(cc2, af[0][mi], &bh4[q * 2]);
                            mma16816(cc2, af[0][mi], &bl4[q * 2]);
                            mma16816(cc2, af[1][mi], &bh4[q * 2]);
                        }
                }
            }
        }

        // tail: g = GLU(acc+b2) -> smem stage0; kpart = g @ W3slice^T
        __syncthreads();
        {
#pragma unroll
            for (int mi = 0; mi < 2; ++mi)
#pragma unroll
                for (int q = 0; q < 2; ++q) {
                    int gcol = bn + cb + q * 8;
                    float bia0 = b2[gcol],       bia1 = b2[gcol + 1];
                    float bib0 = b2[512 + gcol], bib1 = b2[512 + gcol + 1];
                    const float* ca  = acc[mi][q];
                    const float* cbv = acc[mi][2 + q];
                    float g00 = (ca[0] + bia0) / (1.0f + __expf(-(cbv[0] + bib0)));
                    float g01 = (ca[1] + bia1) / (1.0f + __expf(-(cbv[1] + bib1)));
                    float g10 = (ca[2] + bia0) / (1.0f + __expf(-(cbv[2] + bib0)));
                    float g11 = (ca[3] + bia1) / (1.0f + __expf(-(cbv[3] + bib1)));
                    int lr = wm * 32 + (lane >> 2) + mi * 16;
                    int lc = cb + q * 8;
                    __nv_bfloat16 h0, l0, h1, l1;
                    uint32_t o0 = (uint32_t)(lr * ROWE + lc) * 2;
                    bf16split(g00, h0, l0); bf16split(g01, h1, l1);
                    *(__nv_bfloat162*)(smem + o0)       = __nv_bfloat162(h0, h1);
                    *(__nv_bfloat162*)(smem + GLO + o0) = __nv_bfloat162(l0, l1);
                    uint32_t o1 = (uint32_t)((lr + 8) * ROWE + lc) * 2;
                    bf16split(g10, h0, l0); bf16split(g11, h1, l1);
                    *(__nv_bfloat162*)(smem + o1)       = __nv_bfloat162(h0, h1);
                    *(__nv_bfloat162*)(smem + GLO + o1) = __nv_bfloat162(l0, l1);
                }
            __syncthreads();

            if (wid < 8) {
                float accs[4][4];
#pragma unroll
                for (int i = 0; i < 4; ++i)
#pragma unroll
                    for (int j = 0; j < 4; ++j) accs[i][j] = 0.0f;

                const uint32_t a_b = sb + (uint32_t)((wid * 16 + (lane & 15)) * ROWE
                                                     + ((lane >> 4) << 3)) * 2;
                const uint32_t w_b = sb + W3_OFF
                    + (uint32_t)(((lane >> 4) << 3) + (lane & 7)) * W3_ROWB
                    + (uint32_t)((((lane >> 3) & 1) << 3)) * 2;
#pragma unroll
                for (int kk = 0; kk < 4; ++kk) {
                    uint32_t ah[4], al[4];
                    ldsm4(ah, a_b + kk * 32);
                    ldsm4(al, a_b + GLO + kk * 32);
#pragma unroll
                    for (int p = 0; p < 2; ++p) {
                        uint32_t bo = w_b + (uint32_t)(p * 16 * W3_ROWB) + kk * 32;
                        uint32_t bh4[4], bl4[4];
                        ldsm4(bh4, bo);
                        ldsm4(bl4, bo + W3_PREC);
#pragma unroll
                        for (int q = 0; q < 2; ++q) {
                            float* cc2 = accs[p * 2 + q];
                            mma16816(cc2, ah, &bh4[q * 2]);
                            mma16816(cc2, ah, &bl4[q * 2]);
                            mma16816(cc2, al, &bh4[q * 2]);
                        }
                    }
                }
                float* kp = g_kpart + (size_t)bnI * NELEM;
#pragma unroll
                for (int nt = 0; nt < 4; ++nt)
#pragma unroll
                    for (int half = 0; half < 2; ++half) {
                        int lr = wid * 16 + (lane >> 2) + half * 8;
                        int col = nt * 8 + (lane & 3) * 2;
                        *(float2*)(kp + (size_t)(bm + lr) * DDIM + col)
                            = make_float2(accs[nt][half * 2], accs[nt][half * 2 + 1]);
                    }
            }
        }
        __threadfence();
        __syncthreads();
        if (tid == 0) flag_release(&g_kpflag[bm16 * 8 + bnI], target);
    }
}

// ---------------- final RK4 combine ----------------
__global__ __launch_bounds__(256)
void final_update(const float* __restrict__ b3, float dt, float* __restrict__ out) {
    int idx = blockIdx.x * 256 + threadIdx.x;
    int c = idx & 31;
    float kv = b3[c];
#pragma unroll
    for (int b = 0; b < 8; ++b)
        kv += g_kpart[(size_t)b * NELEM + idx];
    out[idx] = g_theta2[1][idx] + (dt / 6.0f) * (g_ksum2[1][idx] + kv);
}

// ---------------- host launcher ----------------
extern "C" void kernel_launch(void* const* d_in, const int* in_sizes, int n_in,
                              void* d_out, int out_size) {
    const float* theta0  = (const float*)d_in[0];
    const float* context = (const float*)d_in[1];
    const float* W1      = (const float*)d_in[2];
    const float* b1      = (const float*)d_in[3];
    const float* W2      = (const float*)d_in[4];
    const float* b2      = (const float*)d_in[5];
    const float* W3      = (const float*)d_in[6];
    const float* b3      = (const float*)d_in[7];
    float* out = (float*)d_out;

    cudaFuncSetAttribute(c0_build, cudaFuncAttributeMaxDynamicSharedMemorySize, GLU_SMEM);
    cudaFuncSetAttribute(persist,  cudaFuncAttributeMaxDynamicSharedMemorySize, GLU_SMEM);

    const float dt = 1.0f / NSTEPS;
    init_all<<<(INIT_TOT + 255) / 256, 256>>>(W1, W2, W3, context, theta0);
    dim3 cgrid(8, 16);
    c0_build<<<cgrid, 512, GLU_SMEM>>>(b1);
    persist<<<128, 512, GLU_SMEM>>>(W1, b2, b3, dt);
    final_update<<<256, 256>>>(b3, dt, out);
}

// round 13
// speedup vs baseline: 1.6169x; 1.4427x over previous
#include <cuda_runtime.h>
#include <cuda_fp16.h>
#include <math.h>
#include <stdint.h>

// ---------------- problem constants ----------------
#define BATCH  2048
#define DDIM   32
#define HID    512
#define NSTEPS 16
#define NELEM  (BATCH * DDIM)

// ---------------- device scratch ----------------
__device__ __align__(16) __half g_h1_hi[BATCH * HID];
__device__ __align__(16) __half g_h1_lo[BATCH * HID];
__device__ __align__(16) float  g_theta2[2][NELEM];
__device__ __align__(16) float  g_ksum2 [2][NELEM];
__device__ __align__(16) float  g_kpart[8 * NELEM];
__device__ __align__(16) __half g_B1t[1024 * 32];      // W1 theta rows, transposed, fp16
__device__ __align__(16) __half g_B1c[1024 * 128];     // W1 ctx rows, transposed, fp16
__device__ __align__(16) __half g_B2 [1024 * HID];     // W2 transposed, fp16
__device__ __align__(16) __half g_W3t[DDIM * HID];     // W3 transposed, fp16
__device__ __align__(16) __half g_ctx_hi[BATCH * 128];
__device__ __align__(16) __half g_ctx_lo[BATCH * 128];
__device__ __align__(16) float  g_C0[BATCH * 1024];    // ctx@W1c + b1 (fp32)

// ---------------- PTX helpers (compute_100-safe) ----------------
__device__ __forceinline__ uint32_t smem_u32(const void* p) {
    uint32_t a;
    asm("{ .reg .u64 t; cvta.to.shared.u64 t, %1; cvt.u32.u64 %0, t; }"
        : "=r"(a) : "l"(p));
    return a;
}
__device__ __forceinline__ void cpasync16(uint32_t saddr, const void* g) {
    asm volatile("cp.async.cg.shared.global [%0], [%1], 16;"
                 :: "r"(saddr), "l"(g) : "memory");
}
#define CP_COMMIT() asm volatile("cp.async.commit_group;" ::: "memory")
#define CP_WAIT0()  asm volatile("cp.async.wait_group 0;" ::: "memory")
#define CP_WAIT1()  asm volatile("cp.async.wait_group 1;" ::: "memory")

__device__ __forceinline__ void ldsm4(uint32_t* r, uint32_t addr) {
    asm volatile("ldmatrix.sync.aligned.m8n8.x4.shared.b16 {%0,%1,%2,%3}, [%4];"
                 : "=r"(r[0]), "=r"(r[1]), "=r"(r[2]), "=r"(r[3]) : "r"(addr));
}
__device__ __forceinline__ void mma16816(float* c, const uint32_t* a, const uint32_t* b) {
    asm volatile("mma.sync.aligned.m16n8k16.row.col.f32.f16.f16.f32 "
                 "{%0,%1,%2,%3}, {%4,%5,%6,%7}, {%8,%9}, {%0,%1,%2,%3};"
                 : "+f"(c[0]), "+f"(c[1]), "+f"(c[2]), "+f"(c[3])
                 : "r"(a[0]), "r"(a[1]), "r"(a[2]), "r"(a[3]),
                   "r"(b[0]), "r"(b[1]));
}
__device__ __forceinline__ void f16split(float v, __half& h, __half& l) {
    h = __float2half_rn(v);
    l = __float2half_rn(v - __half2float(h));
}

// ---------------- merged init kernel ----------------
// segments: [B2: 524288][ctx: 262144][b1c: 131072][theta: 65536][b1t: 32768][w3t: 16384]
#define SEG_B2   524288
#define SEG_CTX  (SEG_B2 + 262144)        // 786432
#define SEG_B1C  (SEG_CTX + 131072)       // 917504
#define SEG_TH   (SEG_B1C + 65536)        // 983040
#define SEG_B1T  (SEG_TH + 32768)         // 1015808
#define SEG_W3   (SEG_B1T + 16384)        // 1032192
#define INIT_TOT SEG_W3

__global__ void init_all(const float* __restrict__ W1, const float* __restrict__ W2,
                         const float* __restrict__ W3, const float* __restrict__ context,
                         const float* __restrict__ theta0) {
    int idx = blockIdx.x * 256 + threadIdx.x;
    if (idx >= INIT_TOT) return;
    if (idx < SEG_B2) {
        int n = idx >> 9, k = idx & 511;
        g_B2[idx] = __float2half_rn(W2[(size_t)k * 1024 + n]);
    } else if (idx < SEG_CTX) {
        int i = idx - SEG_B2;
        __half h, l; f16split(context[i], h, l);
        g_ctx_hi[i] = h; g_ctx_lo[i] = l;
    } else if (idx < SEG_B1C) {
        int i = idx - SEG_CTX;
        int n = i >> 7, k = i & 127;
        g_B1c[i] = __float2half_rn(W1[(size_t)(33 + k) * 1024 + n]);
    } else if (idx < SEG_TH) {
        int i = idx - SEG_B1C;
        g_theta2[0][i] = theta0[i];
    } else if (idx < SEG_B1T) {
        int i = idx - SEG_TH;
        int n = i >> 5, k = i & 31;
        g_B1t[i] = __float2half_rn(W1[(size_t)k * 1024 + n]);
    } else {
        int i = idx - SEG_B1T;
        int n = i >> 9, k = i & 511;
        g_W3t[i] = __float2half_rn(W3[(size_t)k * DDIM + n]);
    }
}

// ---------------- smem layout (consumer + c0) ----------------
#define ROWE  72
#define TILE_B (128 * ROWE * 2)          // 18432
#define OFF_AH 0
#define OFF_AL (TILE_B)
#define OFF_BH (2 * TILE_B)
#define STAGE_B (3 * TILE_B)             // 55296
#define W3_OFF  (3 * STAGE_B)            // 165888
#define W3_ROWB 144
#define GLU_SMEM (W3_OFF + 32 * W3_ROWB) // 170496
#define GLO  (TILE_B)                    // g-lo offset within stage0

// ================= C0 build (once per call): C0 = ctx @ W1[33:161] + b1 =================
__global__ __launch_bounds__(512)
void c0_build(const float* __restrict__ b1) {
    extern __shared__ char smem[];
    const uint32_t sb = smem_u32(smem);
    const int tid  = threadIdx.x;
    const int lane = tid & 31, wid = tid >> 5;
    const int wm = wid & 3, wn = wid >> 2;
    const int bm = blockIdx.y * 128, bn = blockIdx.x * 64;

    float acc[2][4][4];
#pragma unroll
    for (int i = 0; i < 2; ++i)
#pragma unroll
        for (int j = 0; j < 4; ++j)
#pragma unroll
            for (int q = 0; q < 4; ++q) acc[i][j][q] = 0.0f;

    auto issue = [&](int c) {
        const int kc = c * 64;
        const uint32_t st = sb + (uint32_t)((c % 3) * STAGE_B);
#pragma unroll
        for (int p = 0; p < 2; ++p) {
            int slot = p * 512 + tid;
            int row = slot >> 3, cc = slot & 7;
            uint32_t so = (uint32_t)(row * ROWE + cc * 8) * 2;
            cpasync16(st + OFF_AH + so, g_ctx_hi + (size_t)(bm + row) * 128 + kc + cc * 8);
            cpasync16(st + OFF_AL + so, g_ctx_lo + (size_t)(bm + row) * 128 + kc + cc * 8);
            int brow = (row < 64) ? (bn + row) : (448 + bn + row);
            cpasync16(st + OFF_BH + so, g_B1c + (size_t)brow * 128 + kc + cc * 8);
        }
        CP_COMMIT();
    };

    const uint32_t a_off = (uint32_t)((wm * 32 + (lane & 15)) * ROWE
                                      + ((lane >> 4) << 3)) * 2;
    const uint32_t b_off = (uint32_t)((wn * 16 + ((lane >> 4) << 3) + (lane & 7)) * ROWE
                                      + (((lane >> 3) & 1) << 3)) * 2;

    issue(0); issue(1);
    for (int c = 0; c < 2; ++c) {
        if (c == 0) CP_WAIT1(); else CP_WAIT0();
        __syncthreads();
        const uint32_t st = sb + (uint32_t)((c % 3) * STAGE_B);
#pragma unroll
        for (int kk = 0; kk < 4; ++kk) {
            const uint32_t kb = (uint32_t)(kk * 16) * 2;
            uint32_t af[2][2][4];
#pragma unroll
            for (int mi = 0; mi < 2; ++mi) {
                uint32_t o = a_off + (uint32_t)(mi * 16 * ROWE) * 2 + kb;
                ldsm4(af[0][mi], st + OFF_AH + o);
                ldsm4(af[1][mi], st + OFF_AL + o);
            }
#pragma unroll
            for (int h = 0; h < 2; ++h) {
                uint32_t bh4[4];
                uint32_t o = b_off + (uint32_t)(h * 64 * ROWE) * 2 + kb;
                ldsm4(bh4, st + OFF_BH + o);
#pragma unroll
                for (int mi = 0; mi < 2; ++mi)
#pragma unroll
                    for (int q = 0; q < 2; ++q) {
                        float* cc2 = acc[mi][h * 2 + q];
                        mma16816(cc2, af[0][mi], &bh4[q * 2]);
                        mma16816(cc2, af[1][mi], &bh4[q * 2]);
                    }
            }
        }
        __syncthreads();
    }

    const int r0 = bm + wm * 32 + (lane >> 2);
    const int cb = wn * 16 + (lane & 3) * 2;
#pragma unroll
    for (int mi = 0; mi < 2; ++mi)
#pragma unroll
        for (int q = 0; q < 2; ++q) {
            int gcol = bn + cb + q * 8;
            float bia0 = b1[gcol],       bia1 = b1[gcol + 1];
            float bib0 = b1[512 + gcol], bib1 = b1[512 + gcol + 1];
            const float* ca  = acc[mi][q];
            const float* cbv = acc[mi][2 + q];
            int ra = r0 + mi * 16;
            *(float2*)(g_C0 + (size_t)ra * 1024 + gcol)
                = make_float2(ca[0] + bia0, ca[1] + bia1);
            *(float2*)(g_C0 + (size_t)ra * 1024 + 512 + gcol)
                = make_float2(cbv[0] + bib0, cbv[1] + bib1);
            *(float2*)(g_C0 + (size_t)(ra + 8) * 1024 + gcol)
                = make_float2(ca[2] + bia0, ca[3] + bia1);
            *(float2*)(g_C0 + (size_t)(ra + 8) * 1024 + 512 + gcol)
                = make_float2(cbv[2] + bib0, cbv[3] + bib1);
        }
}

// ================= layer1 theta-GEMM + inline RK4 (producer) =================
// grid (8,16), 512 thr; CTA M=128, N=64 per half; K=32 single pass; fp16 2-term.
#define R2 40
#define A1P (128 * R2 * 2)               // 10240
#define SM1 (3 * A1P)                    // A1 hi, A1 lo, B1t single

__global__ __launch_bounds__(512)
void glu1t(const float* __restrict__ W1, const float* __restrict__ b3,
           int it, float tval, float dt, int s_prev, int rd, int wr) {
    extern __shared__ char smem[];
    const uint32_t sb = smem_u32(smem);
    const int tid  = threadIdx.x;
    const int lane = tid & 31, wid = tid >> 5;
    const int wm = wid & 3, wn = wid >> 2;
    const int bm = blockIdx.y * 128, bn = blockIdx.x * 64;

    // B1t loads (128 out-rows x 32 k, fp16 single): 512 slots, 1/thread
    {
        int row = tid >> 2, cc = tid & 3;
        uint32_t so = (uint32_t)(2 * A1P + (row * R2 + cc * 8) * 2);
        int brow = (row < 64) ? (bn + row) : (448 + bn + row);
        cpasync16(sb + so, g_B1t + (size_t)brow * 32 + cc * 8);
    }
    CP_COMMIT();

    // RK4 arg build -> A1 smem (+ state update by bn==0 CTAs)
    {
        int r = tid >> 2, c0 = (tid & 3) * 8;
        size_t base = (size_t)(bm + r) * DDIM + c0;
        float th[8], kv[8], ks[8], arg[8];
        *(float4*)&th[0] = *(const float4*)&g_theta2[rd][base];
        *(float4*)&th[4] = *(const float4*)&g_theta2[rd][base + 4];
        if (it > 0) {
#pragma unroll
            for (int j = 0; j < 8; ++j) kv[j] = b3[c0 + j];
#pragma unroll
            for (int b = 0; b < 8; ++b) {
                float4 v0 = *(const float4*)&g_kpart[(size_t)b * NELEM + base];
                float4 v1 = *(const float4*)&g_kpart[(size_t)b * NELEM + base + 4];
                kv[0] += v0.x; kv[1] += v0.y; kv[2] += v0.z; kv[3] += v0.w;
                kv[4] += v1.x; kv[5] += v1.y; kv[6] += v1.z; kv[7] += v1.w;
            }
            if (s_prev >= 1) {
                *(float4*)&ks[0] = *(const float4*)&g_ksum2[rd][base];
                *(float4*)&ks[4] = *(const float4*)&g_ksum2[rd][base + 4];
            }
#pragma unroll
            for (int j = 0; j < 8; ++j) {
                if (s_prev == 0 || s_prev == 1) arg[j] = th[j] + 0.5f * dt * kv[j];
                else if (s_prev == 2)           arg[j] = th[j] + dt * kv[j];
                else                            arg[j] = th[j] + (dt / 6.0f) * (ks[j] + kv[j]);
            }
            if (blockIdx.x == 0) {
                float ksw[8], thw[8];
#pragma unroll
                for (int j = 0; j < 8; ++j) {
                    if (s_prev == 0)      { ksw[j] = kv[j];                thw[j] = th[j]; }
                    else if (s_prev <= 2) { ksw[j] = ks[j] + 2.0f * kv[j]; thw[j] = th[j]; }
                    else                  { ksw[j] = ks[j] + kv[j];        thw[j] = arg[j]; }
                }
                *(float4*)&g_ksum2[wr][base]      = *(float4*)&ksw[0];
                *(float4*)&g_ksum2[wr][base + 4]  = *(float4*)&ksw[4];
                *(float4*)&g_theta2[wr][base]     = *(float4*)&thw[0];
                *(float4*)&g_theta2[wr][base + 4] = *(float4*)&thw[4];
            }
        } else {
#pragma unroll
            for (int j = 0; j < 8; ++j) arg[j] = th[j];
        }
        uint32_t ao = (uint32_t)(r * R2 + c0) * 2;
#pragma unroll
        for (int j = 0; j < 4; ++j) {
            __half h0, l0, h1, l1;
            f16split(arg[2 * j],     h0, l0);
            f16split(arg[2 * j + 1], h1, l1);
            *(__half2*)(smem + ao + j * 4)       = __halves2half2(h0, h1);
            *(__half2*)(smem + A1P + ao + j * 4) = __halves2half2(l0, l1);
        }
    }
    CP_WAIT0();
    __syncthreads();

    // K=32 mainloop (2-term)
    float acc[2][4][4];
#pragma unroll
    for (int i = 0; i < 2; ++i)
#pragma unroll
        for (int j = 0; j < 4; ++j)
#pragma unroll
            for (int q = 0; q < 4; ++q) acc[i][j][q] = 0.0f;

    const uint32_t a_off = (uint32_t)((wm * 32 + (lane & 15)) * R2
                                      + ((lane >> 4) << 3)) * 2;
    const uint32_t b_off = (uint32_t)(2 * A1P)
        + (uint32_t)((wn * 16 + ((lane >> 4) << 3) + (lane & 7)) * R2
                     + (((lane >> 3) & 1) << 3)) * 2;
#pragma unroll
    for (int kk = 0; kk < 2; ++kk) {
        const uint32_t kb = (uint32_t)(kk * 16) * 2;
        uint32_t af[2][2][4];
#pragma unroll
        for (int mi = 0; mi < 2; ++mi) {
            uint32_t o = a_off + (uint32_t)(mi * 16 * R2) * 2 + kb;
            ldsm4(af[0][mi], sb + o);
            ldsm4(af[1][mi], sb + A1P + o);
        }
#pragma unroll
        for (int h = 0; h < 2; ++h) {
            uint32_t bh4[4];
            uint32_t o = b_off + (uint32_t)(h * 64 * R2) * 2 + kb;
            ldsm4(bh4, sb + o);
#pragma unroll
            for (int mi = 0; mi < 2; ++mi)
#pragma unroll
                for (int q = 0; q < 2; ++q) {
                    float* cc2 = acc[mi][h * 2 + q];
                    mma16816(cc2, af[0][mi], &bh4[q * 2]);
                    mma16816(cc2, af[1][mi], &bh4[q * 2]);
                }
        }
    }

    // epilogue: + C0 + t*W1[32], GLU, write h1 hi/lo (fp16)
    const int r0 = bm + wm * 32 + (lane >> 2);
    const int cb = wn * 16 + (lane & 3) * 2;
    const float* w132 = W1 + (size_t)32 * 1024;
#pragma unroll
    for (int mi = 0; mi < 2; ++mi)
#pragma unroll
        for (int q = 0; q < 2; ++q) {
            int gcol = bn + cb + q * 8;
            int ra = r0 + mi * 16;
            float wa0 = tval * w132[gcol],       wa1 = tval * w132[gcol + 1];
            float wb0 = tval * w132[512 + gcol], wb1 = tval * w132[512 + gcol + 1];
            float2 c0a0 = *(const float2*)&g_C0[(size_t)ra * 1024 + gcol];
            float2 c0b0 = *(const float2*)&g_C0[(size_t)ra * 1024 + 512 + gcol];
            float2 c0a1 = *(const float2*)&g_C0[(size_t)(ra + 8) * 1024 + gcol];
            float2 c0b1 = *(const float2*)&g_C0[(size_t)(ra + 8) * 1024 + 512 + gcol];
            const float* ca  = acc[mi][q];
            const float* cbv = acc[mi][2 + q];
            float g00 = (ca[0] + c0a0.x + wa0) / (1.0f + __expf(-(cbv[0] + c0b0.x + wb0)));
            float g01 = (ca[1] + c0a0.y + wa1) / (1.0f + __expf(-(cbv[1] + c0b0.y + wb1)));
            float g10 = (ca[2] + c0a1.x + wa0) / (1.0f + __expf(-(cbv[2] + c0b1.x + wb0)));
            float g11 = (ca[3] + c0a1.y + wa1) / (1.0f + __expf(-(cbv[3] + c0b1.y + wb1)));
            size_t o0 = (size_t)ra * HID + gcol;
            size_t o1 = (size_t)(ra + 8) * HID + gcol;
            __half h0, l0, h1, l1;
            f16split(g00, h0, l0); f16split(g01, h1, l1);
            *(__half2*)(g_h1_hi + o0) = __halves2half2(h0, h1);
            *(__half2*)(g_h1_lo + o0) = __halves2half2(l0, l1);
            f16split(g10, h0, l0); f16split(g11, h1, l1);
            *(__half2*)(g_h1_hi + o1) = __halves2half2(h0, h1);
            *(__half2*)(g_h1_lo + o1) = __halves2half2(l0, l1);
        }
}

// ================= layer-2 GLU + k3 partial (consumer) =================
// grid (8,16), 512 thr; CTA M=128, N=64 per half; BK=64; fp16 2-term; 3-stage.
__global__ __launch_bounds__(512)
void glu2(const float* __restrict__ b2) {
    extern __shared__ char smem[];
    const uint32_t sb = smem_u32(smem);
    const int tid  = threadIdx.x;
    const int lane = tid & 31, wid = tid >> 5;
    const int wm = wid & 3, wn = wid >> 2;
    const int bm = blockIdx.y * 128, bn = blockIdx.x * 64;

    float acc[2][4][4];
#pragma unroll
    for (int i = 0; i < 2; ++i)
#pragma unroll
        for (int j = 0; j < 4; ++j)
#pragma unroll
            for (int q = 0; q < 4; ++q) acc[i][j][q] = 0.0f;

    auto issue = [&](int c) {
        const int kc = c * 64;
        const uint32_t st = sb + (uint32_t)((c % 3) * STAGE_B);
#pragma unroll
        for (int p = 0; p < 2; ++p) {
            int slot = p * 512 + tid;
            int row = slot >> 3, cc = slot & 7;
            uint32_t so = (uint32_t)(row * ROWE + cc * 8) * 2;
            cpasync16(st + OFF_AH + so, g_h1_hi + (size_t)(bm + row) * HID + kc + cc * 8);
            cpasync16(st + OFF_AL + so, g_h1_lo + (size_t)(bm + row) * HID + kc + cc * 8);
            int brow = (row < 64) ? (bn + row) : (448 + bn + row);
            cpasync16(st + OFF_BH + so, g_B2 + (size_t)brow * HID + kc + cc * 8);
        }
        if (c == 0 && tid < 256) {
            // W3 slice (fp16 single): 32 rows x 64 k
            int row = tid >> 3, cc = tid & 7;
            uint32_t so = (uint32_t)(W3_OFF + row * W3_ROWB + cc * 16);
            cpasync16(sb + so, g_W3t + (size_t)row * HID + bn + cc * 8);
        }
        CP_COMMIT();
    };

    const uint32_t a_off = (uint32_t)((wm * 32 + (lane & 15)) * ROWE
                                      + ((lane >> 4) << 3)) * 2;
    const uint32_t b_off = (uint32_t)((wn * 16 + ((lane >> 4) << 3) + (lane & 7)) * ROWE
                                      + (((lane >> 3) & 1) << 3)) * 2;
    const int cb = wn * 16 + (lane & 3) * 2;

    issue(0); issue(1);

    for (int c = 0; c < 8; ++c) {
        if (c + 1 < 8) CP_WAIT1(); else CP_WAIT0();
        __syncthreads();
        if (c + 2 < 8) issue(c + 2);

        const uint32_t st = sb + (uint32_t)((c % 3) * STAGE_B);
#pragma unroll
        for (int kk = 0; kk < 4; ++kk) {
            const uint32_t kb = (uint32_t)(kk * 16) * 2;
            uint32_t af[2][2][4];
#pragma unroll
            for (int mi = 0; mi < 2; ++mi) {
                uint32_t o = a_off + (uint32_t)(mi * 16 * ROWE) * 2 + kb;
                ldsm4(af[0][mi], st + OFF_AH + o);
                ldsm4(af[1][mi], st + OFF_AL + o);
            }
#pragma unroll
            for (int h = 0; h < 2; ++h) {
                uint32_t bh4[4];
                uint32_t o = b_off + (uint32_t)(h * 64 * ROWE) * 2 + kb;
                ldsm4(bh4, st + OFF_BH + o);
#pragma unroll
                for (int mi = 0; mi < 2; ++mi)
#pragma unroll
                    for (int q = 0; q < 2; ++q) {
                        float* cc2 = acc[mi][h * 2 + q];
                        mma16816(cc2, af[0][mi], &bh4[q * 2]);
                        mma16816(cc2, af[1][mi], &bh4[q * 2]);
                    }
            }
        }
    }

    // tail: g = GLU(acc+b2) -> smem stage0 (hi/lo); kpart = g @ W3slice^T
    __syncthreads();
    {
#pragma unroll
        for (int mi = 0; mi < 2; ++mi)
#pragma unroll
            for (int q = 0; q < 2; ++q) {
                int gcol = bn + cb + q * 8;
                float bia0 = b2[gcol],       bia1 = b2[gcol + 1];
                float bib0 = b2[512 + gcol], bib1 = b2[512 + gcol + 1];
                const float* ca  = acc[mi][q];
                const float* cbv = acc[mi][2 + q];
                float g00 = (ca[0] + bia0) / (1.0f + __expf(-(cbv[0] + bib0)));
                float g01 = (ca[1] + bia1) / (1.0f + __expf(-(cbv[1] + bib1)));
                float g10 = (ca[2] + bia0) / (1.0f + __expf(-(cbv[2] + bib0)));
                float g11 = (ca[3] + bia1) / (1.0f + __expf(-(cbv[3] + bib1)));
                int lr = wm * 32 + (lane >> 2) + mi * 16;
                int lc = cb + q * 8;
                __half h0, l0, h1, l1;
                uint32_t o0 = (uint32_t)(lr * ROWE + lc) * 2;
                f16split(g00, h0, l0); f16split(g01, h1, l1);
                *(__half2*)(smem + o0)       = __halves2half2(h0, h1);
                *(__half2*)(smem + GLO + o0) = __halves2half2(l0, l1);
                uint32_t o1 = (uint32_t)((lr + 8) * ROWE + lc) * 2;
                f16split(g10, h0, l0); f16split(g11, h1, l1);
                *(__half2*)(smem + o1)       = __halves2half2(h0, h1);
                *(__half2*)(smem + GLO + o1) = __halves2half2(l0, l1);
            }
        __syncthreads();

        if (wid < 8) {
            float accs[4][4];
#pragma unroll
            for (int i = 0; i < 4; ++i)
#pragma unroll
                for (int j = 0; j < 4; ++j) accs[i][j] = 0.0f;

            const uint32_t a_b = sb + (uint32_t)((wid * 16 + (lane & 15)) * ROWE
                                                 + ((lane >> 4) << 3)) * 2;
            const uint32_t w_b = sb + W3_OFF
                + (uint32_t)(((lane >> 4) << 3) + (lane & 7)) * W3_ROWB
                + (uint32_t)((((lane >> 3) & 1) << 3)) * 2;
#pragma unroll
            for (int kk = 0; kk < 4; ++kk) {
                uint32_t ah[4], al[4];
                ldsm4(ah, a_b + kk * 32);
                ldsm4(al, a_b + GLO + kk * 32);
#pragma unroll
                for (int p = 0; p < 2; ++p) {
                    uint32_t bo = w_b + (uint32_t)(p * 16 * W3_ROWB) + kk * 32;
                    uint32_t bh4[4];
                    ldsm4(bh4, bo);
#pragma unroll
                    for (int q = 0; q < 2; ++q) {
                        float* cc2 = accs[p * 2 + q];
                        mma16816(cc2, ah, &bh4[q * 2]);
                        mma16816(cc2, al, &bh4[q * 2]);
                    }
                }
            }
            float* kp = g_kpart + (size_t)blockIdx.x * NELEM;
#pragma unroll
            for (int nt = 0; nt < 4; ++nt)
#pragma unroll
                for (int half = 0; half < 2; ++half) {
                    int lr = wid * 16 + (lane >> 2) + half * 8;
                    int col = nt * 8 + (lane & 3) * 2;
                    *(float2*)(kp + (size_t)(bm + lr) * DDIM + col)
                        = make_float2(accs[nt][half * 2], accs[nt][half * 2 + 1]);
                }
        }
    }
}

// ---------------- final RK4 combine ----------------
__global__ __launch_bounds__(256)
void final_update(const float* __restrict__ b3, float dt, float* __restrict__ out) {
    int idx = blockIdx.x * 256 + threadIdx.x;
    int c = idx & 31;
    float kv = b3[c];
#pragma unroll
    for (int b = 0; b < 8; ++b)
        kv += g_kpart[(size_t)b * NELEM + idx];
    out[idx] = g_theta2[1][idx] + (dt / 6.0f) * (g_ksum2[1][idx] + kv);
}

// ---------------- host launcher ----------------
extern "C" void kernel_launch(void* const* d_in, const int* in_sizes, int n_in,
                              void* d_out, int out_size) {
    const float* theta0  = (const float*)d_in[0];
    const float* context = (const float*)d_in[1];
    const float* W1      = (const float*)d_in[2];
    const float* b1      = (const float*)d_in[3];
    const float* W2      = (const float*)d_in[4];
    const float* b2      = (const float*)d_in[5];
    const float* W3      = (const float*)d_in[6];
    const float* b3      = (const float*)d_in[7];
    float* out = (float*)d_out;

    cudaFuncSetAttribute(c0_build, cudaFuncAttributeMaxDynamicSharedMemorySize, GLU_SMEM);
    cudaFuncSetAttribute(glu2,     cudaFuncAttributeMaxDynamicSharedMemorySize, GLU_SMEM);
    cudaFuncSetAttribute(glu1t,    cudaFuncAttributeMaxDynamicSharedMemorySize, SM1);

    const float dt = 1.0f / NSTEPS;
    init_all<<<(INIT_TOT + 255) / 256, 256>>>(W1, W2, W3, context, theta0);

    dim3 ggrid(8, 16);
    c0_build<<<ggrid, 512, GLU_SMEM>>>(b1);

    for (int it = 0; it < NSTEPS * 4; ++it) {
        int s = it & 3;
        float tval = (float)(it >> 2) * dt + ((s == 0) ? 0.0f : (s < 3 ? 0.5f * dt : dt));
        int s_prev = (it - 1) & 3;
        int rd = (it == 0) ? 0 : ((it - 1) & 1);
        int wr = it & 1;
        glu1t<<<ggrid, 512, SM1>>>(W1, b3, it, tval, dt, s_prev, rd, wr);
        glu2<<<ggrid, 512, GLU_SMEM>>>(b2);
    }
    final_update<<<256, 256>>>(b3, dt, out);
}

// round 14
// speedup vs baseline: 2.2543x; 1.3942x over previous
#include <cuda_runtime.h>
#include <cuda_fp16.h>
#include <math.h>
#include <stdint.h>

// ---------------- problem constants ----------------
#define BATCH  2048
#define DDIM   32
#define HID    512
#define NSTEPS 16
#define NELEM  (BATCH * DDIM)

// ---------------- device scratch ----------------
__device__ __align__(16) __half g_h1[BATCH * HID];     // single fp16 activations
__device__ __align__(16) float  g_theta2[2][NELEM];
__device__ __align__(16) float  g_ksum2 [2][NELEM];
__device__ __align__(16) float  g_kpart[8 * NELEM];
__device__ __align__(16) __half g_B1t[1024 * 32];      // W1 theta rows, transposed, fp16
__device__ __align__(16) __half g_B1c[1024 * 128];     // W1 ctx rows, transposed, fp16
__device__ __align__(16) __half g_B2 [1024 * HID];     // W2 transposed, fp16
__device__ __align__(16) __half g_W3t[DDIM * HID];     // W3 transposed, fp16
__device__ __align__(16) __half g_ctx_hi[BATCH * 128];
__device__ __align__(16) __half g_ctx_lo[BATCH * 128];
__device__ __align__(16) float  g_C0[BATCH * 1024];    // ctx@W1c + b1 (fp32)

// ---------------- PTX helpers (compute_100-safe) ----------------
__device__ __forceinline__ uint32_t smem_u32(const void* p) {
    uint32_t a;
    asm("{ .reg .u64 t; cvta.to.shared.u64 t, %1; cvt.u32.u64 %0, t; }"
        : "=r"(a) : "l"(p));
    return a;
}
__device__ __forceinline__ void cpasync16(uint32_t saddr, const void* g) {
    asm volatile("cp.async.cg.shared.global [%0], [%1], 16;"
                 :: "r"(saddr), "l"(g) : "memory");
}
#define CP_COMMIT() asm volatile("cp.async.commit_group;" ::: "memory")
#define CP_WAIT0()  asm volatile("cp.async.wait_group 0;" ::: "memory")
#define CP_WAIT1()  asm volatile("cp.async.wait_group 1;" ::: "memory")

__device__ __forceinline__ void ldsm4(uint32_t* r, uint32_t addr) {
    asm volatile("ldmatrix.sync.aligned.m8n8.x4.shared.b16 {%0,%1,%2,%3}, [%4];"
                 : "=r"(r[0]), "=r"(r[1]), "=r"(r[2]), "=r"(r[3]) : "r"(addr));
}
__device__ __forceinline__ void mma16816(float* c, const uint32_t* a, const uint32_t* b) {
    asm volatile("mma.sync.aligned.m16n8k16.row.col.f32.f16.f16.f32 "
                 "{%0,%1,%2,%3}, {%4,%5,%6,%7}, {%8,%9}, {%0,%1,%2,%3};"
                 : "+f"(c[0]), "+f"(c[1]), "+f"(c[2]), "+f"(c[3])
                 : "r"(a[0]), "r"(a[1]), "r"(a[2]), "r"(a[3]),
                   "r"(b[0]), "r"(b[1]));
}
__device__ __forceinline__ void f16split(float v, __half& h, __half& l) {
    h = __float2half_rn(v);
    l = __float2half_rn(v - __half2float(h));
}

// ---------------- merged init kernel ----------------
#define SEG_B2   524288
#define SEG_CTX  (SEG_B2 + 262144)        // 786432
#define SEG_B1C  (SEG_CTX + 131072)       // 917504
#define SEG_TH   (SEG_B1C + 65536)        // 983040
#define SEG_B1T  (SEG_TH + 32768)         // 1015808
#define SEG_W3   (SEG_B1T + 16384)        // 1032192
#define INIT_TOT SEG_W3

__global__ void init_all(const float* __restrict__ W1, const float* __restrict__ W2,
                         const float* __restrict__ W3, const float* __restrict__ context,
                         const float* __restrict__ theta0) {
    int idx = blockIdx.x * 256 + threadIdx.x;
    if (idx >= INIT_TOT) return;
    if (idx < SEG_B2) {
        int n = idx >> 9, k = idx & 511;
        g_B2[idx] = __float2half_rn(W2[(size_t)k * 1024 + n]);
    } else if (idx < SEG_CTX) {
        int i = idx - SEG_B2;
        __half h, l; f16split(context[i], h, l);
        g_ctx_hi[i] = h; g_ctx_lo[i] = l;
    } else if (idx < SEG_B1C) {
        int i = idx - SEG_CTX;
        int n = i >> 7, k = i & 127;
        g_B1c[i] = __float2half_rn(W1[(size_t)(33 + k) * 1024 + n]);
    } else if (idx < SEG_TH) {
        int i = idx - SEG_B1C;
        g_theta2[0][i] = theta0[i];
    } else if (idx < SEG_B1T) {
        int i = idx - SEG_TH;
        int n = i >> 5, k = i & 31;
        g_B1t[i] = __float2half_rn(W1[(size_t)k * 1024 + n]);
    } else {
        int i = idx - SEG_B1T;
        int n = i >> 9, k = i & 511;
        g_W3t[i] = __float2half_rn(W3[(size_t)k * DDIM + n]);
    }
}

// ---------------- smem layouts ----------------
#define ROWE  72
#define TILE_B (128 * ROWE * 2)          // 18432
// glu2 (single-fp16 A): stage = [A][B]
#define OFF_A 0
#define OFF_B (TILE_B)
#define STAGE_B (2 * TILE_B)             // 36864
#define W3_OFF  (3 * STAGE_B)            // 110592
#define W3_ROWB 144
#define GLU_SMEM (W3_OFF + 32 * W3_ROWB) // 115200
// c0_build (2-term ctx): stage = [AH][AL][B]
#define C0_AH 0
#define C0_AL (TILE_B)
#define C0_B  (2 * TILE_B)
#define C0STG (3 * TILE_B)               // 55296
#define C0_SMEM (3 * C0STG)              // 165888

// ================= C0 build (once per call): C0 = ctx @ W1[33:161] + b1 =================
__global__ __launch_bounds__(512)
void c0_build(const float* __restrict__ b1) {
    extern __shared__ char smem[];
    const uint32_t sb = smem_u32(smem);
    const int tid  = threadIdx.x;
    const int lane = tid & 31, wid = tid >> 5;
    const int wm = wid & 3, wn = wid >> 2;
    const int bm = blockIdx.y * 128, bn = blockIdx.x * 64;

    float acc[2][4][4];
#pragma unroll
    for (int i = 0; i < 2; ++i)
#pragma unroll
        for (int j = 0; j < 4; ++j)
#pragma unroll
            for (int q = 0; q < 4; ++q) acc[i][j][q] = 0.0f;

    auto issue = [&](int c) {
        const int kc = c * 64;
        const uint32_t st = sb + (uint32_t)((c % 3) * C0STG);
#pragma unroll
        for (int p = 0; p < 2; ++p) {
            int slot = p * 512 + tid;
            int row = slot >> 3, cc = slot & 7;
            uint32_t so = (uint32_t)(row * ROWE + cc * 8) * 2;
            cpasync16(st + C0_AH + so, g_ctx_hi + (size_t)(bm + row) * 128 + kc + cc * 8);
            cpasync16(st + C0_AL + so, g_ctx_lo + (size_t)(bm + row) * 128 + kc + cc * 8);
            int brow = (row < 64) ? (bn + row) : (448 + bn + row);
            cpasync16(st + C0_B + so, g_B1c + (size_t)brow * 128 + kc + cc * 8);
        }
        CP_COMMIT();
    };

    const uint32_t a_off = (uint32_t)((wm * 32 + (lane & 15)) * ROWE
                                      + ((lane >> 4) << 3)) * 2;
    const uint32_t b_off = (uint32_t)((wn * 16 + ((lane >> 4) << 3) + (lane & 7)) * ROWE
                                      + (((lane >> 3) & 1) << 3)) * 2;

    issue(0); issue(1);
    for (int c = 0; c < 2; ++c) {
        if (c == 0) CP_WAIT1(); else CP_WAIT0();
        __syncthreads();
        const uint32_t st = sb + (uint32_t)((c % 3) * C0STG);
#pragma unroll
        for (int kk = 0; kk < 4; ++kk) {
            const uint32_t kb = (uint32_t)(kk * 16) * 2;
            uint32_t af[2][2][4];
#pragma unroll
            for (int mi = 0; mi < 2; ++mi) {
                uint32_t o = a_off + (uint32_t)(mi * 16 * ROWE) * 2 + kb;
                ldsm4(af[0][mi], st + C0_AH + o);
                ldsm4(af[1][mi], st + C0_AL + o);
            }
#pragma unroll
            for (int h = 0; h < 2; ++h) {
                uint32_t bh4[4];
                uint32_t o = b_off + (uint32_t)(h * 64 * ROWE) * 2 + kb;
                ldsm4(bh4, st + C0_B + o);
#pragma unroll
                for (int mi = 0; mi < 2; ++mi)
#pragma unroll
                    for (int q = 0; q < 2; ++q) {
                        float* cc2 = acc[mi][h * 2 + q];
                        mma16816(cc2, af[0][mi], &bh4[q * 2]);
                        mma16816(cc2, af[1][mi], &bh4[q * 2]);
                    }
            }
        }
        __syncthreads();
    }

    const int r0 = bm + wm * 32 + (lane >> 2);
    const int cb = wn * 16 + (lane & 3) * 2;
#pragma unroll
    for (int mi = 0; mi < 2; ++mi)
#pragma unroll
        for (int q = 0; q < 2; ++q) {
            int gcol = bn + cb + q * 8;
            float bia0 = b1[gcol],       bia1 = b1[gcol + 1];
            float bib0 = b1[512 + gcol], bib1 = b1[512 + gcol + 1];
            const float* ca  = acc[mi][q];
            const float* cbv = acc[mi][2 + q];
            int ra = r0 + mi * 16;
            *(float2*)(g_C0 + (size_t)ra * 1024 + gcol)
                = make_float2(ca[0] + bia0, ca[1] + bia1);
            *(float2*)(g_C0 + (size_t)ra * 1024 + 512 + gcol)
                = make_float2(cbv[0] + bib0, cbv[1] + bib1);
            *(float2*)(g_C0 + (size_t)(ra + 8) * 1024 + gcol)
                = make_float2(ca[2] + bia0, ca[3] + bia1);
            *(float2*)(g_C0 + (size_t)(ra + 8) * 1024 + 512 + gcol)
                = make_float2(cbv[2] + bib0, cbv[3] + bib1);
        }
}

// ================= layer1 theta-GEMM + inline RK4 (producer) =================
// A1 (theta args) 2-term fp16 (compounding state needs accuracy); B1t single.
#define R2 40
#define A1P (128 * R2 * 2)               // 10240
#define SM1 (3 * A1P)

__global__ __launch_bounds__(512)
void glu1t(const float* __restrict__ W1, const float* __restrict__ b3,
           int it, float tval, float dt, int s_prev, int rd, int wr) {
    extern __shared__ char smem[];
    const uint32_t sb = smem_u32(smem);
    const int tid  = threadIdx.x;
    const int lane = tid & 31, wid = tid >> 5;
    const int wm = wid & 3, wn = wid >> 2;
    const int bm = blockIdx.y * 128, bn = blockIdx.x * 64;

    // B1t loads (128 out-rows x 32 k, fp16 single)
    {
        int row = tid >> 2, cc = tid & 3;
        uint32_t so = (uint32_t)(2 * A1P + (row * R2 + cc * 8) * 2);
        int brow = (row < 64) ? (bn + row) : (448 + bn + row);
        cpasync16(sb + so, g_B1t + (size_t)brow * 32 + cc * 8);
    }
    CP_COMMIT();

    // RK4 arg build -> A1 smem (+ state update by bn==0 CTAs)
    {
        int r = tid >> 2, c0 = (tid & 3) * 8;
        size_t base = (size_t)(bm + r) * DDIM + c0;
        float th[8], kv[8], ks[8], arg[8];
        *(float4*)&th[0] = *(const float4*)&g_theta2[rd][base];
        *(float4*)&th[4] = *(const float4*)&g_theta2[rd][base + 4];
        if (it > 0) {
#pragma unroll
            for (int j = 0; j < 8; ++j) kv[j] = b3[c0 + j];
#pragma unroll
            for (int b = 0; b < 8; ++b) {
                float4 v0 = *(const float4*)&g_kpart[(size_t)b * NELEM + base];
                float4 v1 = *(const float4*)&g_kpart[(size_t)b * NELEM + base + 4];
                kv[0] += v0.x; kv[1] += v0.y; kv[2] += v0.z; kv[3] += v0.w;
                kv[4] += v1.x; kv[5] += v1.y; kv[6] += v1.z; kv[7] += v1.w;
            }
            if (s_prev >= 1) {
                *(float4*)&ks[0] = *(const float4*)&g_ksum2[rd][base];
                *(float4*)&ks[4] = *(const float4*)&g_ksum2[rd][base + 4];
            }
#pragma unroll
            for (int j = 0; j < 8; ++j) {
                if (s_prev == 0 || s_prev == 1) arg[j] = th[j] + 0.5f * dt * kv[j];
                else if (s_prev == 2)           arg[j] = th[j] + dt * kv[j];
                else                            arg[j] = th[j] + (dt / 6.0f) * (ks[j] + kv[j]);
            }
            if (blockIdx.x == 0) {
                float ksw[8], thw[8];
#pragma unroll
                for (int j = 0; j < 8; ++j) {
                    if (s_prev == 0)      { ksw[j] = kv[j];                thw[j] = th[j]; }
                    else if (s_prev <= 2) { ksw[j] = ks[j] + 2.0f * kv[j]; thw[j] = th[j]; }
                    else                  { ksw[j] = ks[j] + kv[j];        thw[j] = arg[j]; }
                }
                *(float4*)&g_ksum2[wr][base]      = *(float4*)&ksw[0];
                *(float4*)&g_ksum2[wr][base + 4]  = *(float4*)&ksw[4];
                *(float4*)&g_theta2[wr][base]     = *(float4*)&thw[0];
                *(float4*)&g_theta2[wr][base + 4] = *(float4*)&thw[4];
            }
        } else {
#pragma unroll
            for (int j = 0; j < 8; ++j) arg[j] = th[j];
        }
        uint32_t ao = (uint32_t)(r * R2 + c0) * 2;
#pragma unroll
        for (int j = 0; j < 4; ++j) {
            __half h0, l0, h1, l1;
            f16split(arg[2 * j],     h0, l0);
            f16split(arg[2 * j + 1], h1, l1);
            *(__half2*)(smem + ao + j * 4)       = __halves2half2(h0, h1);
            *(__half2*)(smem + A1P + ao + j * 4) = __halves2half2(l0, l1);
        }
    }
    CP_WAIT0();
    __syncthreads();

    // K=32 mainloop (A 2-term, B single)
    float acc[2][4][4];
#pragma unroll
    for (int i = 0; i < 2; ++i)
#pragma unroll
        for (int j = 0; j < 4; ++j)
#pragma unroll
            for (int q = 0; q < 4; ++q) acc[i][j][q] = 0.0f;

    const uint32_t a_off = (uint32_t)((wm * 32 + (lane & 15)) * R2
                                      + ((lane >> 4) << 3)) * 2;
    const uint32_t b_off = (uint32_t)(2 * A1P)
        + (uint32_t)((wn * 16 + ((lane >> 4) << 3) + (lane & 7)) * R2
                     + (((lane >> 3) & 1) << 3)) * 2;
#pragma unroll
    for (int kk = 0; kk < 2; ++kk) {
        const uint32_t kb = (uint32_t)(kk * 16) * 2;
        uint32_t af[2][2][4];
#pragma unroll
        for (int mi = 0; mi < 2; ++mi) {
            uint32_t o = a_off + (uint32_t)(mi * 16 * R2) * 2 + kb;
            ldsm4(af[0][mi], sb + o);
            ldsm4(af[1][mi], sb + A1P + o);
        }
#pragma unroll
        for (int h = 0; h < 2; ++h) {
            uint32_t bh4[4];
            uint32_t o = b_off + (uint32_t)(h * 64 * R2) * 2 + kb;
            ldsm4(bh4, sb + o);
#pragma unroll
            for (int mi = 0; mi < 2; ++mi)
#pragma unroll
                for (int q = 0; q < 2; ++q) {
                    float* cc2 = acc[mi][h * 2 + q];
                    mma16816(cc2, af[0][mi], &bh4[q * 2]);
                    mma16816(cc2, af[1][mi], &bh4[q * 2]);
                }
        }
    }

    // epilogue: + C0 + t*W1[32], GLU, write h1 (single fp16)
    const int r0 = bm + wm * 32 + (lane >> 2);
    const int cb = wn * 16 + (lane & 3) * 2;
    const float* w132 = W1 + (size_t)32 * 1024;
#pragma unroll
    for (int mi = 0; mi < 2; ++mi)
#pragma unroll
        for (int q = 0; q < 2; ++q) {
            int gcol = bn + cb + q * 8;
            int ra = r0 + mi * 16;
            float wa0 = tval * w132[gcol],       wa1 = tval * w132[gcol + 1];
            float wb0 = tval * w132[512 + gcol], wb1 = tval * w132[512 + gcol + 1];
            float2 c0a0 = *(const float2*)&g_C0[(size_t)ra * 1024 + gcol];
            float2 c0b0 = *(const float2*)&g_C0[(size_t)ra * 1024 + 512 + gcol];
            float2 c0a1 = *(const float2*)&g_C0[(size_t)(ra + 8) * 1024 + gcol];
            float2 c0b1 = *(const float2*)&g_C0[(size_t)(ra + 8) * 1024 + 512 + gcol];
            const float* ca  = acc[mi][q];
            const float* cbv = acc[mi][2 + q];
            float g00 = (ca[0] + c0a0.x + wa0) / (1.0f + __expf(-(cbv[0] + c0b0.x + wb0)));
            float g01 = (ca[1] + c0a0.y + wa1) / (1.0f + __expf(-(cbv[1] + c0b0.y + wb1)));
            float g10 = (ca[2] + c0a1.x + wa0) / (1.0f + __expf(-(cbv[2] + c0b1.x + wb0)));
            float g11 = (ca[3] + c0a1.y + wa1) / (1.0f + __expf(-(cbv[3] + c0b1.y + wb1)));
            size_t o0 = (size_t)ra * HID + gcol;
            size_t o1 = (size_t)(ra + 8) * HID + gcol;
            *(__half2*)(g_h1 + o0) = __halves2half2(__float2half_rn(g00), __float2half_rn(g01));
            *(__half2*)(g_h1 + o1) = __halves2half2(__float2half_rn(g10), __float2half_rn(g11));
        }
}

// ================= layer-2 GLU + k3 partial (consumer) =================
// Single-fp16 A; 1-term MMA; 3-stage pipeline.
__global__ __launch_bounds__(512)
void glu2(const float* __restrict__ b2) {
    extern __shared__ char smem[];
    const uint32_t sb = smem_u32(smem);
    const int tid  = threadIdx.x;
    const int lane = tid & 31, wid = tid >> 5;
    const int wm = wid & 3, wn = wid >> 2;
    const int bm = blockIdx.y * 128, bn = blockIdx.x * 64;

    float acc[2][4][4];
#pragma unroll
    for (int i = 0; i < 2; ++i)
#pragma unroll
        for (int j = 0; j < 4; ++j)
#pragma unroll
            for (int q = 0; q < 4; ++q) acc[i][j][q] = 0.0f;

    auto issue = [&](int c) {
        const int kc = c * 64;
        const uint32_t st = sb + (uint32_t)((c % 3) * STAGE_B);
#pragma unroll
        for (int p = 0; p < 2; ++p) {
            int slot = p * 512 + tid;
            int row = slot >> 3, cc = slot & 7;
            uint32_t so = (uint32_t)(row * ROWE + cc * 8) * 2;
            cpasync16(st + OFF_A + so, g_h1 + (size_t)(bm + row) * HID + kc + cc * 8);
            int brow = (row < 64) ? (bn + row) : (448 + bn + row);
            cpasync16(st + OFF_B + so, g_B2 + (size_t)brow * HID + kc + cc * 8);
        }
        if (c == 0 && tid < 256) {
            int row = tid >> 3, cc = tid & 7;
            uint32_t so = (uint32_t)(W3_OFF + row * W3_ROWB + cc * 16);
            cpasync16(sb + so, g_W3t + (size_t)row * HID + bn + cc * 8);
        }
        CP_COMMIT();
    };

    const uint32_t a_off = (uint32_t)((wm * 32 + (lane & 15)) * ROWE
                                      + ((lane >> 4) << 3)) * 2;
    const uint32_t b_off = (uint32_t)((wn * 16 + ((lane >> 4) << 3) + (lane & 7)) * ROWE
                                      + (((lane >> 3) & 1) << 3)) * 2;
    const int cb = wn * 16 + (lane & 3) * 2;

    issue(0); issue(1);

    for (int c = 0; c < 8; ++c) {
        if (c + 1 < 8) CP_WAIT1(); else CP_WAIT0();
        __syncthreads();
        if (c + 2 < 8) issue(c + 2);

        const uint32_t st = sb + (uint32_t)((c % 3) * STAGE_B);
#pragma unroll
        for (int kk = 0; kk < 4; ++kk) {
            const uint32_t kb = (uint32_t)(kk * 16) * 2;
            uint32_t af[2][4];
#pragma unroll
            for (int mi = 0; mi < 2; ++mi) {
                uint32_t o = a_off + (uint32_t)(mi * 16 * ROWE) * 2 + kb;
                ldsm4(af[mi], st + OFF_A + o);
            }
#pragma unroll
            for (int h = 0; h < 2; ++h) {
                uint32_t bh4[4];
                uint32_t o = b_off + (uint32_t)(h * 64 * ROWE) * 2 + kb;
                ldsm4(bh4, st + OFF_B + o);
#pragma unroll
                for (int mi = 0; mi < 2; ++mi)
#pragma unroll
                    for (int q = 0; q < 2; ++q)
                        mma16816(acc[mi][h * 2 + q], af[mi], &bh4[q * 2]);
            }
        }
    }

    // tail: g = GLU(acc+b2) -> smem stage0 (single fp16); kpart = g @ W3slice^T
    __syncthreads();
    {
#pragma unroll
        for (int mi = 0; mi < 2; ++mi)
#pragma unroll
            for (int q = 0; q < 2; ++q) {
                int gcol = bn + cb + q * 8;
                float bia0 = b2[gcol],       bia1 = b2[gcol + 1];
                float bib0 = b2[512 + gcol], bib1 = b2[512 + gcol + 1];
                const float* ca  = acc[mi][q];
                const float* cbv = acc[mi][2 + q];
                float g00 = (ca[0] + bia0) / (1.0f + __expf(-(cbv[0] + bib0)));
                float g01 = (ca[1] + bia1) / (1.0f + __expf(-(cbv[1] + bib1)));
                float g10 = (ca[2] + bia0) / (1.0f + __expf(-(cbv[2] + bib0)));
                float g11 = (ca[3] + bia1) / (1.0f + __expf(-(cbv[3] + bib1)));
                int lr = wm * 32 + (lane >> 2) + mi * 16;
                int lc = cb + q * 8;
                uint32_t o0 = (uint32_t)(lr * ROWE + lc) * 2;
                *(__half2*)(smem + o0) = __halves2half2(__float2half_rn(g00),
                                                        __float2half_rn(g01));
                uint32_t o1 = (uint32_t)((lr + 8) * ROWE + lc) * 2;
                *(__half2*)(smem + o1) = __halves2half2(__float2half_rn(g10),
                                                        __float2half_rn(g11));
            }
        __syncthreads();

        if (wid < 8) {
            float accs[4][4];
#pragma unroll
            for (int i = 0; i < 4; ++i)
#pragma unroll
                for (int j = 0; j < 4; ++j) accs[i][j] = 0.0f;

            const uint32_t a_b = sb + (uint32_t)((wid * 16 + (lane & 15)) * ROWE
                                                 + ((lane >> 4) << 3)) * 2;
            const uint32_t w_b = sb + W3_OFF
                + (uint32_t)(((lane >> 4) << 3) + (lane & 7)) * W3_ROWB
                + (uint32_t)((((lane >> 3) & 1) << 3)) * 2;
#pragma unroll
            for (int kk = 0; kk < 4; ++kk) {
                uint32_t ah[4];
                ldsm4(ah, a_b + kk * 32);
#pragma unroll
                for (int p = 0; p < 2; ++p) {
                    uint32_t bo = w_b + (uint32_t)(p * 16 * W3_ROWB) + kk * 32;
                    uint32_t bh4[4];
                    ldsm4(bh4, bo);
#pragma unroll
                    for (int q = 0; q < 2; ++q)
                        mma16816(accs[p * 2 + q], ah, &bh4[q * 2]);
                }
            }
            float* kp = g_kpart + (size_t)blockIdx.x * NELEM;
#pragma unroll
            for (int nt = 0; nt < 4; ++nt)
#pragma unroll
                for (int half = 0; half < 2; ++half) {
                    int lr = wid * 16 + (lane >> 2) + half * 8;
                    int col = nt * 8 + (lane & 3) * 2;
                    *(float2*)(kp + (size_t)(bm + lr) * DDIM + col)
                        = make_float2(accs[nt][half * 2], accs[nt][half * 2 + 1]);
                }
        }
    }
}

// ---------------- final RK4 combine ----------------
__global__ __launch_bounds__(256)
void final_update(const float* __restrict__ b3, float dt, float* __restrict__ out) {
    int idx = blockIdx.x * 256 + threadIdx.x;
    int c = idx & 31;
    float kv = b3[c];
#pragma unroll
    for (int b = 0; b < 8; ++b)
        kv += g_kpart[(size_t)b * NELEM + idx];
    out[idx] = g_theta2[1][idx] + (dt / 6.0f) * (g_ksum2[1][idx] + kv);
}

// ---------------- host launcher ----------------
extern "C" void kernel_launch(void* const* d_in, const int* in_sizes, int n_in,
                              void* d_out, int out_size) {
    const float* theta0  = (const float*)d_in[0];
    const float* context = (const float*)d_in[1];
    const float* W1      = (const float*)d_in[2];
    const float* b1      = (const float*)d_in[3];
    const float* W2      = (const float*)d_in[4];
    const float* b2      = (const float*)d_in[5];
    const float* W3      = (const float*)d_in[6];
    const float* b3      = (const float*)d_in[7];
    float* out = (float*)d_out;

    cudaFuncSetAttribute(c0_build, cudaFuncAttributeMaxDynamicSharedMemorySize, C0_SMEM);
    cudaFuncSetAttribute(glu2,     cudaFuncAttributeMaxDynamicSharedMemorySize, GLU_SMEM);
    cudaFuncSetAttribute(glu1t,    cudaFuncAttributeMaxDynamicSharedMemorySize, SM1);

    const float dt = 1.0f / NSTEPS;
    init_all<<<(INIT_TOT + 255) / 256, 256>>>(W1, W2, W3, context, theta0);

    dim3 ggrid(8, 16);
    c0_build<<<ggrid, 512, C0_SMEM>>>(b1);

    for (int it = 0; it < NSTEPS * 4; ++it) {
        int s = it & 3;
        float tval = (float)(it >> 2) * dt + ((s == 0) ? 0.0f : (s < 3 ? 0.5f * dt : dt));
        int s_prev = (it - 1) & 3;
        int rd = (it == 0) ? 0 : ((it - 1) & 1);
        int wr = it & 1;
        glu1t<<<ggrid, 512, SM1>>>(W1, b3, it, tval, dt, s_prev, rd, wr);
        glu2<<<ggrid, 512, GLU_SMEM>>>(b2);
    }
    final_update<<<256, 256>>>(b3, dt, out);
}